// round 1
// baseline (speedup 1.0000x reference)
#include <cuda_runtime.h>
#include <math.h>

#define NN 50000
#define DD 128
#define EE 800000

// ---------------- device scratch (no allocations allowed) ----------------
__device__ __align__(16) float g_t [NN*DD];
__device__ __align__(16) float g_h [NN*DD];
__device__ __align__(16) float g_h2[NN*DD];
__device__ __align__(16) float g_x [NN*DD];
__device__ __align__(16) float g_d0[NN*DD];
__device__ __align__(16) float g_d1[NN*DD];

__device__ int g_cntc[NN], g_cntr[NN];
__device__ int g_colptr[NN+1], g_rowptr[NN+1];
__device__ int g_nextc[NN], g_nextr[NN];
__device__ int g_erow_c[EE], g_eid_c[EE];
__device__ int g_ecol_r[EE], g_eid_r[EE];
__device__ float g_c0[EE], g_c1[EE], g_c2[EE];
__device__ float g_ec0[EE], g_ec1[EE];

__device__ float g_maskf[NN], g_weights[NN], g_dis[NN], g_s[NN], g_aggr[NN];
__device__ float g_score[NN], g_scale[NN];
__device__ unsigned g_key[NN];
__device__ unsigned g_bins[256];
__device__ unsigned g_prefix, g_krem;
__device__ float g_pnorm;

// ---------------- setup kernels ----------------
__global__ void k_init() {
    int i = blockIdx.x * blockDim.x + threadIdx.x;
    if (i < NN) { g_cntc[i] = 0; g_cntr[i] = 0; g_maskf[i] = 1.f; g_weights[i] = 1.f; }
}

__global__ void k_edge_hist(const int* __restrict__ row, const int* __restrict__ col) {
    int e = blockIdx.x * blockDim.x + threadIdx.x;
    if (e < EE) { atomicAdd(&g_cntc[col[e]], 1); atomicAdd(&g_cntr[row[e]], 1); }
}

// single-block exclusive scan of cnt[NN] -> ptr[NN+1], also copies into nxt[]
__global__ void k_scan(const int* __restrict__ cnt, int* __restrict__ ptr, int* __restrict__ nxt) {
    __shared__ int ss[1024];
    int t = threadIdx.x;
    const int CH = (NN + 1023) / 1024;  // 49
    int base = t * CH;
    int s = 0;
    for (int i = 0; i < CH; i++) { int idx = base + i; if (idx < NN) s += cnt[idx]; }
    ss[t] = s;
    __syncthreads();
    for (int off = 1; off < 1024; off <<= 1) {
        int v = (t >= off) ? ss[t - off] : 0;
        __syncthreads();
        ss[t] += v;
        __syncthreads();
    }
    int run = (t == 0) ? 0 : ss[t - 1];
    for (int i = 0; i < CH; i++) {
        int idx = base + i;
        if (idx < NN) { ptr[idx] = run; nxt[idx] = run; run += cnt[idx]; }
    }
    if (base <= NN - 1 && (NN - 1) < base + CH) ptr[NN] = run;
}

__global__ void k_fill(const int* __restrict__ row, const int* __restrict__ col) {
    int e = blockIdx.x * blockDim.x + threadIdx.x;
    if (e < EE) {
        int r = row[e], c = col[e];
        int p = atomicAdd(&g_nextc[c], 1); g_erow_c[p] = r; g_eid_c[p] = e;
        int q = atomicAdd(&g_nextr[r], 1); g_ecol_r[q] = c; g_eid_r[q] = e;
    }
}

// deg over active out-edges (row-CSR), then dis = deg^-1/2 and s = weights/deg
__global__ void k_degdis() {
    int w = (blockIdx.x * blockDim.x + threadIdx.x) >> 5;
    int lane = threadIdx.x & 31;
    if (w >= NN) return;
    int s0 = g_rowptr[w], e0 = g_rowptr[w + 1];
    float sum = 0.f;
    for (int j = s0 + lane; j < e0; j += 32) sum += g_maskf[g_ecol_r[j]];
    for (int o = 16; o; o >>= 1) sum += __shfl_xor_sync(0xffffffffu, sum, o);
    if (lane == 0) {
        float deg = g_maskf[w] * sum;
        g_dis[w] = (deg > 0.f) ? rsqrtf(deg) : 0.f;
        g_s[w]   = (deg > 0.f) ? g_weights[w] / deg : 0.f;
    }
}

__global__ void k_coef(const int* __restrict__ row, const int* __restrict__ col,
                       float* __restrict__ cf) {
    int e = blockIdx.x * blockDim.x + threadIdx.x;
    if (e < EE) cf[e] = g_dis[row[e]] * g_dis[col[e]];
}

// ---------------- dense GEMM: out = X @ W + b   (NN x DD) @ (DD x DD) ----------------
__global__ void k_gemm(const float* __restrict__ X, const float* __restrict__ W,
                       const float* __restrict__ bias, float* __restrict__ out) {
    __shared__ __align__(16) float xs[64 * 32];
    __shared__ __align__(16) float ws[32 * 128];
    int tid  = threadIdx.x;          // 256
    int warp = tid >> 5;             // 0..7 -> 8-row group
    int lane = tid & 31;             // 4 cols each
    int row0 = blockIdx.x * 64;

    float4 acc[8];
#pragma unroll
    for (int rr = 0; rr < 8; rr++) acc[rr] = make_float4(0.f, 0.f, 0.f, 0.f);

    for (int kb = 0; kb < 128; kb += 32) {
        // load X tile 64x32 (512 float4)
        for (int i = tid; i < 512; i += 256) {
            int r = i >> 3, c4 = i & 7;
            int gr = row0 + r;
            float4 v = make_float4(0.f, 0.f, 0.f, 0.f);
            if (gr < NN) v = *(const float4*)(X + (size_t)gr * 128 + kb + c4 * 4);
            *(float4*)(xs + r * 32 + c4 * 4) = v;
        }
        // load W tile 32x128 (1024 float4)
        for (int i = tid; i < 1024; i += 256) {
            int kr = i >> 5, c4 = i & 31;
            *(float4*)(ws + kr * 128 + c4 * 4) =
                *(const float4*)(W + (size_t)(kb + kr) * 128 + c4 * 4);
        }
        __syncthreads();
#pragma unroll 4
        for (int k = 0; k < 32; k++) {
            float4 wv = *(const float4*)(ws + k * 128 + lane * 4);
#pragma unroll
            for (int rr = 0; rr < 8; rr++) {
                float xv = xs[(warp * 8 + rr) * 32 + k];
                acc[rr].x = fmaf(xv, wv.x, acc[rr].x);
                acc[rr].y = fmaf(xv, wv.y, acc[rr].y);
                acc[rr].z = fmaf(xv, wv.z, acc[rr].z);
                acc[rr].w = fmaf(xv, wv.w, acc[rr].w);
            }
        }
        __syncthreads();
    }
    float4 bv = *(const float4*)(bias + lane * 4);
#pragma unroll
    for (int rr = 0; rr < 8; rr++) {
        int gr = row0 + warp * 8 + rr;
        if (gr < NN) {
            float4 o;
            o.x = acc[rr].x + bv.x; o.y = acc[rr].y + bv.y;
            o.z = acc[rr].z + bv.z; o.w = acc[rr].w + bv.w;
            *(float4*)(out + (size_t)gr * 128 + lane * 4) = o;
        }
    }
}

// ---------------- CSR SpMM: out[n,:] = init[n,:] + sum_j cf[eid[j]] * in[nbr[j],:] ----------------
__global__ void k_spmm(const int* __restrict__ ptr, const int* __restrict__ nbr,
                       const int* __restrict__ eid, const float* __restrict__ cf,
                       const float* __restrict__ in, const float* __restrict__ init,
                       float* __restrict__ out) {
    int w = (blockIdx.x * blockDim.x + threadIdx.x) >> 5;
    int lane = threadIdx.x & 31;
    if (w >= NN) return;
    int s0 = ptr[w], e0 = ptr[w + 1];
    float4 acc;
    if (init) acc = *(const float4*)(init + (size_t)w * DD + lane * 4);
    else      acc = make_float4(0.f, 0.f, 0.f, 0.f);
    for (int j = s0; j < e0; j++) {
        float c = cf[eid[j]];
        if (c != 0.f) {
            const float4 v = *(const float4*)(in + (size_t)nbr[j] * DD + lane * 4);
            acc.x = fmaf(c, v.x, acc.x);
            acc.y = fmaf(c, v.y, acc.y);
            acc.z = fmaf(c, v.z, acc.z);
            acc.w = fmaf(c, v.w, acc.w);
        }
    }
    *(float4*)(out + (size_t)w * DD + lane * 4) = acc;
}

// ---------------- cal_ew ----------------
__global__ void k_aggr() {  // aggr[n] = mask[n]*sum_colCSR s[row] + 1e-12
    int w = (blockIdx.x * blockDim.x + threadIdx.x) >> 5;
    int lane = threadIdx.x & 31;
    if (w >= NN) return;
    int s0 = g_colptr[w], e0 = g_colptr[w + 1];
    float sum = 0.f;
    for (int j = s0 + lane; j < e0; j += 32) sum += g_s[g_erow_c[j]];
    for (int o = 16; o; o >>= 1) sum += __shfl_xor_sync(0xffffffffu, sum, o);
    if (lane == 0) g_aggr[w] = g_maskf[w] * sum + 1e-12f;
}

__global__ void k_ec(const int* __restrict__ row, const int* __restrict__ col,
                     float* __restrict__ ec) {
    int e = blockIdx.x * blockDim.x + threadIdx.x;
    if (e < EE) {
        int c = col[e];
        ec[e] = g_s[row[e]] * g_maskf[c] / g_aggr[c];
    }
}

// ---------------- top-k ----------------
__global__ void k_pnorm(const float* __restrict__ p) {
    __shared__ float sh[128];
    int t = threadIdx.x;
    float v = p[t];
    sh[t] = v * v;
    __syncthreads();
    for (int o = 64; o; o >>= 1) { if (t < o) sh[t] += sh[t + o]; __syncthreads(); }
    if (t == 0) g_pnorm = sqrtf(sh[0]);
}

__global__ void k_score(const float* __restrict__ h, const float* __restrict__ p) {
    int w = (blockIdx.x * blockDim.x + threadIdx.x) >> 5;
    int lane = threadIdx.x & 31;
    if (w >= NN) return;
    const float4 hv = *(const float4*)(h + (size_t)w * DD + lane * 4);
    const float4 pv = *(const float4*)(p + lane * 4);
    float d = hv.x * pv.x + hv.y * pv.y + hv.z * pv.z + hv.w * pv.w;
    for (int o = 16; o; o >>= 1) d += __shfl_xor_sync(0xffffffffu, d, o);
    if (lane == 0) {
        float sc = d / g_pnorm;
        g_score[w] = sc;
        unsigned u = __float_as_uint(sc);
        unsigned key = (u & 0x80000000u) ? ~u : (u | 0x80000000u);
        g_key[w] = (g_maskf[w] > 0.f) ? key : 0u;
    }
}

__global__ void k_topk_init(unsigned k) {
    int t = threadIdx.x;
    if (t < 256) g_bins[t] = 0u;
    if (t == 0) { g_prefix = 0u; g_krem = k; }
}

__global__ void k_hist(int pass) {
    __shared__ unsigned hb[256];
    int t = threadIdx.x;
    if (t < 256) hb[t] = 0u;
    __syncthreads();
    unsigned pref = g_prefix;
    int shift = 24 - 8 * pass;
    for (int n = blockIdx.x * blockDim.x + t; n < NN; n += gridDim.x * blockDim.x) {
        unsigned key = g_key[n];
        bool ok = (pass == 0) || ((key >> (32 - 8 * pass)) == pref);
        if (ok) atomicAdd(&hb[(key >> shift) & 255u], 1u);
    }
    __syncthreads();
    if (t < 256 && hb[t]) atomicAdd(&g_bins[t], hb[t]);
}

__global__ void k_select() {
    if (threadIdx.x == 0) {
        unsigned cum = 0;
        int b = 255;
        for (; b >= 0; b--) {
            unsigned c = g_bins[b];
            if (cum + c >= g_krem) break;
            cum += c;
        }
        if (b < 0) b = 0;
        g_prefix = (g_prefix << 8) | (unsigned)b;
        g_krem -= cum;
        for (int i = 0; i < 256; i++) g_bins[i] = 0u;
    }
}

__global__ void k_kept() {
    int n = blockIdx.x * blockDim.x + threadIdx.x;
    if (n < NN) {
        unsigned thr = g_prefix;
        float kept = (g_key[n] >= thr) ? 1.f : 0.f;
        g_maskf[n] = kept;
        g_scale[n] = (kept != 0.f) ? tanhf(g_score[n]) : 0.f;
        g_weights[n] = g_aggr[n] * kept;
    }
}

__global__ void k_scalex(const float* __restrict__ in, float* __restrict__ out) {
    int i = blockIdx.x * blockDim.x + threadIdx.x;
    if (i < NN * DD) out[i] = in[i] * g_scale[i >> 7];
}

// ---------------- host sequence ----------------
extern "C" void kernel_launch(void* const* d_in, const int* in_sizes, int n_in,
                              void* d_out, int out_size) {
    const float* x_in = (const float*)d_in[0];
    const int*   ei   = (const int*)d_in[1];
    const int*   row  = ei;
    const int*   col  = ei + EE;
    const float* Wd = (const float*)d_in[2];
    const float* bd = (const float*)d_in[3];
    const float* Wu = (const float*)d_in[4];
    const float* bu = (const float*)d_in[5];
    const float* Wb = (const float*)d_in[6];
    const float* bb = (const float*)d_in[7];
    const float* pv = (const float*)d_in[8];
    float* out = (float*)d_out;

    void *pt, *ph, *ph2, *px, *pd0, *pd1;
    void *pc0, *pc1, *pc2, *pec0, *pec1;
    void *pcolptr, *prowptr, *perowc, *peidc, *pecolr, *peidr, *pcntc, *pcntr, *pnextc, *pnextr;
    cudaGetSymbolAddress(&pt,  g_t);   cudaGetSymbolAddress(&ph,  g_h);
    cudaGetSymbolAddress(&ph2, g_h2);  cudaGetSymbolAddress(&px,  g_x);
    cudaGetSymbolAddress(&pd0, g_d0);  cudaGetSymbolAddress(&pd1, g_d1);
    cudaGetSymbolAddress(&pc0, g_c0);  cudaGetSymbolAddress(&pc1, g_c1);
    cudaGetSymbolAddress(&pc2, g_c2);  cudaGetSymbolAddress(&pec0, g_ec0);
    cudaGetSymbolAddress(&pec1, g_ec1);
    cudaGetSymbolAddress(&pcolptr, g_colptr); cudaGetSymbolAddress(&prowptr, g_rowptr);
    cudaGetSymbolAddress(&perowc, g_erow_c);  cudaGetSymbolAddress(&peidc,  g_eid_c);
    cudaGetSymbolAddress(&pecolr, g_ecol_r);  cudaGetSymbolAddress(&peidr,  g_eid_r);
    cudaGetSymbolAddress(&pcntc, g_cntc);     cudaGetSymbolAddress(&pcntr, g_cntr);
    cudaGetSymbolAddress(&pnextc, g_nextc);   cudaGetSymbolAddress(&pnextr, g_nextr);

    float *t = (float*)pt, *h = (float*)ph, *h2 = (float*)ph2, *x = (float*)px;
    float *d0 = (float*)pd0, *d1 = (float*)pd1;
    float *c0 = (float*)pc0, *c1 = (float*)pc1, *c2 = (float*)pc2;
    float *ec0 = (float*)pec0, *ec1 = (float*)pec1;
    int *colptr = (int*)pcolptr, *rowptr = (int*)prowptr;
    int *erowc = (int*)perowc, *eidc = (int*)peidc;
    int *ecolr = (int*)pecolr, *eidr = (int*)peidr;
    int *cntc = (int*)pcntc, *cntr = (int*)pcntr;
    int *nextc = (int*)pnextc, *nextr = (int*)pnextr;

    const int GN  = (NN + 255) / 256;        // 196
    const int GE  = (EE + 255) / 256;        // 3125
    const int GW  = (NN * 32 + 255) / 256;   // 6250  (warp per node)
    const int GND = (NN * DD + 255) / 256;   // 25000
    const int GG  = (NN + 63) / 64;          // 782

    // ---- setup: CSR build + level-0 norm ----
    k_init<<<GN, 256>>>();
    k_edge_hist<<<GE, 256>>>(row, col);
    k_scan<<<1, 1024>>>(cntc, colptr, nextc);
    k_scan<<<1, 1024>>>(cntr, rowptr, nextr);
    k_fill<<<GE, 256>>>(row, col);
    k_degdis<<<GW, 256>>>();
    k_coef<<<GE, 256>>>(row, col, c0);

    auto GCN = [&](const float* in, const float* W, const float* b,
                   const float* cf, const float* init, float* o) {
        k_gemm<<<GG, 256>>>(in, W, b, t);
        k_spmm<<<GW, 256>>>(colptr, erowc, eidc, cf, t, init, o);
    };
    auto TOPK = [&](const float* hin, const float* p, unsigned k, float* xout) {
        k_pnorm<<<1, 128>>>(p);
        k_score<<<GW, 256>>>(hin, p);
        k_topk_init<<<1, 256>>>(k);
        for (int pass = 0; pass < 4; pass++) {
            k_hist<<<GN, 256>>>(pass);
            k_select<<<1, 32>>>();
        }
        k_kept<<<GN, 256>>>();
        k_scalex<<<GND, 256>>>(hin, xout);
    };

    // ---- down layer 0 ----
    GCN(x_in, Wd + 0 * DD * DD, bd + 0 * DD, c0, nullptr, h);
    GCN(h,    Wd + 1 * DD * DD, bd + 1 * DD, c0, nullptr, d0);
    k_aggr<<<GW, 256>>>();
    k_ec<<<GE, 256>>>(row, col, ec0);
    k_spmm<<<GW, 256>>>(colptr, erowc, eidc, ec0, d0, nullptr, h2);
    TOPK(h2, pv, 25000u, x);
    k_degdis<<<GW, 256>>>();
    k_coef<<<GE, 256>>>(row, col, c1);

    // ---- down layer 1 ----
    GCN(x, Wd + 2 * DD * DD, bd + 2 * DD, c1, nullptr, h);
    GCN(h, Wd + 3 * DD * DD, bd + 3 * DD, c1, nullptr, d1);
    k_aggr<<<GW, 256>>>();
    k_ec<<<GE, 256>>>(row, col, ec1);
    k_spmm<<<GW, 256>>>(colptr, erowc, eidc, ec1, d1, nullptr, h2);
    TOPK(h2, pv + DD, 12500u, x);
    k_degdis<<<GW, 256>>>();
    k_coef<<<GE, 256>>>(row, col, c2);

    // ---- bottom ----
    GCN(x, Wb + 0 * DD * DD, bb + 0 * DD, c2, nullptr, h);
    GCN(h, Wb + 1 * DD * DD, bb + 1 * DD, c2, nullptr, x);

    // ---- up layer 0 (uses level-1 masks; residual d1) ----
    k_spmm<<<GW, 256>>>(rowptr, ecolr, eidr, ec1, x, nullptr, h);
    GCN(h,  Wu + 0 * DD * DD, bu + 0 * DD, c1, nullptr, h2);
    GCN(h2, Wu + 1 * DD * DD, bu + 1 * DD, c1, d1, x);

    // ---- up layer 1 (uses level-0 masks; residual d0) -> final output ----
    k_spmm<<<GW, 256>>>(rowptr, ecolr, eidr, ec0, x, nullptr, h);
    GCN(h,  Wu + 2 * DD * DD, bu + 2 * DD, c0, nullptr, h2);
    GCN(h2, Wu + 3 * DD * DD, bu + 3 * DD, c0, d0, out);
}

// round 2
// speedup vs baseline: 1.1781x; 1.1781x over previous
#include <cuda_runtime.h>
#include <math.h>

#define NN 50000
#define DD 128
#define EE 800000

// ---------------- device scratch (no allocations allowed) ----------------
__device__ __align__(16) float g_t [NN*DD];
__device__ __align__(16) float g_h [NN*DD];
__device__ __align__(16) float g_h2[NN*DD];
__device__ __align__(16) float g_x [NN*DD];
__device__ __align__(16) float g_d0[NN*DD];
__device__ __align__(16) float g_d1[NN*DD];

__device__ int g_cntc[NN], g_cntr[NN];
__device__ int g_colptr[NN+1], g_rowptr[NN+1];
__device__ int g_nextc[NN], g_nextr[NN];
__device__ int g_erow_c[EE], g_eid_c[EE];
__device__ int g_ecol_r[EE], g_eid_r[EE];
__device__ float g_c0[EE], g_c1[EE], g_c2[EE];
__device__ float g_ec0[EE], g_ec1[EE];

__device__ int g_bsc[256], g_bsr[256], g_boc[256], g_bor[256];

__device__ float g_maskf[NN], g_weights[NN], g_dis[NN], g_s[NN], g_aggr[NN];
__device__ float g_score[NN], g_scale[NN];
__device__ unsigned g_key[NN];
__device__ unsigned g_bins[256];
__device__ unsigned g_prefix, g_krem;
__device__ float g_pnorm;

// ---------------- setup kernels ----------------
__global__ void k_init() {
    int i = blockIdx.x * blockDim.x + threadIdx.x;
    if (i < NN) { g_cntc[i] = 0; g_cntr[i] = 0; g_maskf[i] = 1.f; g_weights[i] = 1.f; }
}

__global__ void k_edge_hist(const int* __restrict__ row, const int* __restrict__ col) {
    int e = blockIdx.x * blockDim.x + threadIdx.x;
    if (e < EE) { atomicAdd(&g_cntc[col[e]], 1); atomicAdd(&g_cntr[row[e]], 1); }
}

// ------- parallel scan: block sums -> scan sums -> local scan + offset -------
__global__ void k_bsum() {
    __shared__ int sc[8], sr[8];
    int t = threadIdx.x;
    int i = blockIdx.x * 256 + t;
    int vc = (i < NN) ? g_cntc[i] : 0;
    int vr = (i < NN) ? g_cntr[i] : 0;
    for (int o = 16; o; o >>= 1) {
        vc += __shfl_xor_sync(0xffffffffu, vc, o);
        vr += __shfl_xor_sync(0xffffffffu, vr, o);
    }
    if ((t & 31) == 0) { sc[t >> 5] = vc; sr[t >> 5] = vr; }
    __syncthreads();
    if (t == 0) {
        int ac = 0, ar = 0;
        for (int w = 0; w < 8; w++) { ac += sc[w]; ar += sr[w]; }
        g_bsc[blockIdx.x] = ac; g_bsr[blockIdx.x] = ar;
    }
}

__global__ void k_bscan(int nblk) {   // 1 block, 256 threads: exclusive scan of block sums
    __shared__ int s1[8], s2[8];
    int t = threadIdx.x, lane = t & 31, w = t >> 5;
    int vc = (t < nblk) ? g_bsc[t] : 0;
    int vr = (t < nblk) ? g_bsr[t] : 0;
    int ic = vc, ir = vr;
    for (int o = 1; o < 32; o <<= 1) {
        int nc = __shfl_up_sync(0xffffffffu, ic, o);
        int nr = __shfl_up_sync(0xffffffffu, ir, o);
        if (lane >= o) { ic += nc; ir += nr; }
    }
    if (lane == 31) { s1[w] = ic; s2[w] = ir; }
    __syncthreads();
    if (w == 0) {
        int a = (lane < 8) ? s1[lane] : 0;
        int b = (lane < 8) ? s2[lane] : 0;
        for (int o = 1; o < 8; o <<= 1) {
            int na = __shfl_up_sync(0xffffffffu, a, o);
            int nb = __shfl_up_sync(0xffffffffu, b, o);
            if (lane >= o) { a += na; b += nb; }
        }
        if (lane < 8) { s1[lane] = a; s2[lane] = b; }
    }
    __syncthreads();
    int offc = (w == 0) ? 0 : s1[w - 1];
    int offr = (w == 0) ? 0 : s2[w - 1];
    if (t < nblk) { g_boc[t] = offc + ic - vc; g_bor[t] = offr + ir - vr; }
}

__device__ __forceinline__ int blk_exscan(int v, int* ws) {
    __syncthreads();
    int lane = threadIdx.x & 31, w = threadIdx.x >> 5;
    int inc = v;
    for (int o = 1; o < 32; o <<= 1) {
        int n = __shfl_up_sync(0xffffffffu, inc, o);
        if (lane >= o) inc += n;
    }
    if (lane == 31) ws[w] = inc;
    __syncthreads();
    if (w == 0) {
        int s = (lane < 8) ? ws[lane] : 0;
        for (int o = 1; o < 8; o <<= 1) {
            int n = __shfl_up_sync(0xffffffffu, s, o);
            if (lane >= o) s += n;
        }
        if (lane < 8) ws[lane] = s;
    }
    __syncthreads();
    int woff = (w == 0) ? 0 : ws[w - 1];
    return woff + inc - v;
}

__global__ void k_scan3() {
    __shared__ int ws[8];
    int t = threadIdx.x;
    int i = blockIdx.x * 256 + t;
    int vc = (i < NN) ? g_cntc[i] : 0;
    int vr = (i < NN) ? g_cntr[i] : 0;
    int exc = blk_exscan(vc, ws);
    int exr = blk_exscan(vr, ws);
    if (i < NN) {
        int pc = g_boc[blockIdx.x] + exc; g_colptr[i] = pc; g_nextc[i] = pc;
        int pr = g_bor[blockIdx.x] + exr; g_rowptr[i] = pr; g_nextr[i] = pr;
    }
    if (i == 0) { g_colptr[NN] = EE; g_rowptr[NN] = EE; }
}

__global__ void k_fill(const int* __restrict__ row, const int* __restrict__ col) {
    int e = blockIdx.x * blockDim.x + threadIdx.x;
    if (e < EE) {
        int r = row[e], c = col[e];
        int p = atomicAdd(&g_nextc[c], 1); g_erow_c[p] = r; g_eid_c[p] = e;
        int q = atomicAdd(&g_nextr[r], 1); g_ecol_r[q] = c; g_eid_r[q] = e;
    }
}

__global__ void k_degdis() {
    int w = (blockIdx.x * blockDim.x + threadIdx.x) >> 5;
    int lane = threadIdx.x & 31;
    if (w >= NN) return;
    int s0 = g_rowptr[w], e0 = g_rowptr[w + 1];
    float sum = 0.f;
    for (int j = s0 + lane; j < e0; j += 32) sum += g_maskf[g_ecol_r[j]];
    for (int o = 16; o; o >>= 1) sum += __shfl_xor_sync(0xffffffffu, sum, o);
    if (lane == 0) {
        float deg = g_maskf[w] * sum;
        g_dis[w] = (deg > 0.f) ? rsqrtf(deg) : 0.f;
        g_s[w]   = (deg > 0.f) ? g_weights[w] / deg : 0.f;
    }
}

__global__ void k_coef(const int* __restrict__ row, const int* __restrict__ col,
                       float* __restrict__ cf) {
    int e = blockIdx.x * blockDim.x + threadIdx.x;
    if (e < EE) cf[e] = g_dis[row[e]] * g_dis[col[e]];
}

// ---------------- tensor-core GEMM (3xTF32): out = X @ W + b ----------------
__device__ __forceinline__ float f2tf(float a) {
    unsigned u;
    asm("cvt.rna.tf32.f32 %0, %1;" : "=r"(u) : "f"(a));
    return __uint_as_float(u);
}

__device__ __forceinline__ void mma_tf32(float* d, const unsigned* a, unsigned b0, unsigned b1) {
    asm volatile(
        "mma.sync.aligned.m16n8k8.row.col.f32.tf32.tf32.f32 "
        "{%0,%1,%2,%3}, {%4,%5,%6,%7}, {%8,%9}, {%0,%1,%2,%3};"
        : "+f"(d[0]), "+f"(d[1]), "+f"(d[2]), "+f"(d[3])
        : "r"(a[0]), "r"(a[1]), "r"(a[2]), "r"(a[3]), "r"(b0), "r"(b1));
}

__global__ void __launch_bounds__(256, 1)
k_gemm_tc(const float* __restrict__ X, const float* __restrict__ W,
          const float* __restrict__ bias, float* __restrict__ out) {
    __shared__ __align__(16) float As[2][128][20];   // [hi/lo][m][k], pad 20
    __shared__ __align__(16) float Bs[2][16][132];   // [hi/lo][k][n], pad 132
    int tid  = threadIdx.x;
    int lane = tid & 31;
    int warp = tid >> 5;             // 8 warps: 4 (m) x 2 (n)
    int wm = warp & 3;               // m group: 32 rows
    int wn = warp >> 2;              // n group: 64 cols
    int gid = lane >> 2;             // 0..7
    int tig = lane & 3;              // 0..3
    int row0 = blockIdx.x * 128;

    float acc[2][8][4];
#pragma unroll
    for (int mt = 0; mt < 2; mt++)
#pragma unroll
        for (int nt = 0; nt < 8; nt++)
#pragma unroll
            for (int q = 0; q < 4; q++) acc[mt][nt][q] = 0.f;

    for (int kb = 0; kb < 8; kb++) {           // K chunks of 16
        // A tile 128x16: 512 float4 loads
#pragma unroll
        for (int ii = 0; ii < 2; ii++) {
            int i = tid + ii * 256;
            int r = i >> 2, c4 = i & 3;
            int gr = row0 + r;
            float4 v = make_float4(0.f, 0.f, 0.f, 0.f);
            if (gr < NN) v = *(const float4*)(X + (size_t)gr * 128 + kb * 16 + c4 * 4);
            float4 hi, lo;
            hi.x = f2tf(v.x); lo.x = f2tf(v.x - hi.x);
            hi.y = f2tf(v.y); lo.y = f2tf(v.y - hi.y);
            hi.z = f2tf(v.z); lo.z = f2tf(v.z - hi.z);
            hi.w = f2tf(v.w); lo.w = f2tf(v.w - hi.w);
            *(float4*)&As[0][r][c4 * 4] = hi;
            *(float4*)&As[1][r][c4 * 4] = lo;
        }
        // B tile 16x128: 512 float4 loads
#pragma unroll
        for (int ii = 0; ii < 2; ii++) {
            int i = tid + ii * 256;
            int r = i >> 5, c4 = i & 31;
            float4 v = *(const float4*)(W + (size_t)(kb * 16 + r) * 128 + c4 * 4);
            float4 hi, lo;
            hi.x = f2tf(v.x); lo.x = f2tf(v.x - hi.x);
            hi.y = f2tf(v.y); lo.y = f2tf(v.y - hi.y);
            hi.z = f2tf(v.z); lo.z = f2tf(v.z - hi.z);
            hi.w = f2tf(v.w); lo.w = f2tf(v.w - hi.w);
            *(float4*)&Bs[0][r][c4 * 4] = hi;
            *(float4*)&Bs[1][r][c4 * 4] = lo;
        }
        __syncthreads();

#pragma unroll
        for (int ks = 0; ks < 2; ks++) {
            int k0 = ks * 8;
            unsigned ah[2][4], al[2][4];
#pragma unroll
            for (int mt = 0; mt < 2; mt++) {
                int r = wm * 32 + mt * 16 + gid;
                int c = k0 + tig;
                ah[mt][0] = __float_as_uint(As[0][r][c]);
                ah[mt][1] = __float_as_uint(As[0][r + 8][c]);
                ah[mt][2] = __float_as_uint(As[0][r][c + 4]);
                ah[mt][3] = __float_as_uint(As[0][r + 8][c + 4]);
                al[mt][0] = __float_as_uint(As[1][r][c]);
                al[mt][1] = __float_as_uint(As[1][r + 8][c]);
                al[mt][2] = __float_as_uint(As[1][r][c + 4]);
                al[mt][3] = __float_as_uint(As[1][r + 8][c + 4]);
            }
#pragma unroll
            for (int nt = 0; nt < 8; nt++) {
                int kk = k0 + tig;
                int nn0 = wn * 64 + nt * 8 + gid;
                unsigned bh0 = __float_as_uint(Bs[0][kk][nn0]);
                unsigned bh1 = __float_as_uint(Bs[0][kk + 4][nn0]);
                unsigned bl0 = __float_as_uint(Bs[1][kk][nn0]);
                unsigned bl1 = __float_as_uint(Bs[1][kk + 4][nn0]);
#pragma unroll
                for (int mt = 0; mt < 2; mt++) {
                    mma_tf32(acc[mt][nt], ah[mt], bh0, bh1);
                    mma_tf32(acc[mt][nt], ah[mt], bl0, bl1);
                    mma_tf32(acc[mt][nt], al[mt], bh0, bh1);
                }
            }
        }
        __syncthreads();
    }

    // epilogue: bias + store
#pragma unroll
    for (int nt = 0; nt < 8; nt++) {
        int c = wn * 64 + nt * 8 + tig * 2;
        float b0 = __ldg(bias + c), b1 = __ldg(bias + c + 1);
#pragma unroll
        for (int mt = 0; mt < 2; mt++) {
            int r = row0 + wm * 32 + mt * 16 + gid;
            if (r < NN) {
                float2 o0 = make_float2(acc[mt][nt][0] + b0, acc[mt][nt][1] + b1);
                *(float2*)(out + (size_t)r * 128 + c) = o0;
            }
            if (r + 8 < NN) {
                float2 o1 = make_float2(acc[mt][nt][2] + b0, acc[mt][nt][3] + b1);
                *(float2*)(out + (size_t)(r + 8) * 128 + c) = o1;
            }
        }
    }
}

// ---------------- CSR SpMM ----------------
__global__ void k_spmm(const int* __restrict__ ptr, const int* __restrict__ nbr,
                       const int* __restrict__ eid, const float* __restrict__ cf,
                       const float* __restrict__ in, const float* __restrict__ init,
                       float* __restrict__ out) {
    int w = (blockIdx.x * blockDim.x + threadIdx.x) >> 5;
    int lane = threadIdx.x & 31;
    if (w >= NN) return;
    int s0 = ptr[w], e0 = ptr[w + 1];
    float4 acc;
    if (init) acc = *(const float4*)(init + (size_t)w * DD + lane * 4);
    else      acc = make_float4(0.f, 0.f, 0.f, 0.f);
    for (int j = s0; j < e0; j++) {
        float c = cf[eid[j]];
        if (c != 0.f) {
            const float4 v = *(const float4*)(in + (size_t)nbr[j] * DD + lane * 4);
            acc.x = fmaf(c, v.x, acc.x);
            acc.y = fmaf(c, v.y, acc.y);
            acc.z = fmaf(c, v.z, acc.z);
            acc.w = fmaf(c, v.w, acc.w);
        }
    }
    *(float4*)(out + (size_t)w * DD + lane * 4) = acc;
}

// ---------------- cal_ew ----------------
__global__ void k_aggr() {
    int w = (blockIdx.x * blockDim.x + threadIdx.x) >> 5;
    int lane = threadIdx.x & 31;
    if (w >= NN) return;
    int s0 = g_colptr[w], e0 = g_colptr[w + 1];
    float sum = 0.f;
    for (int j = s0 + lane; j < e0; j += 32) sum += g_s[g_erow_c[j]];
    for (int o = 16; o; o >>= 1) sum += __shfl_xor_sync(0xffffffffu, sum, o);
    if (lane == 0) g_aggr[w] = g_maskf[w] * sum + 1e-12f;
}

__global__ void k_ec(const int* __restrict__ row, const int* __restrict__ col,
                     float* __restrict__ ec) {
    int e = blockIdx.x * blockDim.x + threadIdx.x;
    if (e < EE) {
        int c = col[e];
        ec[e] = g_s[row[e]] * g_maskf[c] / g_aggr[c];
    }
}

// ---------------- top-k ----------------
__global__ void k_pnorm(const float* __restrict__ p) {
    __shared__ float sh[128];
    int t = threadIdx.x;
    float v = p[t];
    sh[t] = v * v;
    __syncthreads();
    for (int o = 64; o; o >>= 1) { if (t < o) sh[t] += sh[t + o]; __syncthreads(); }
    if (t == 0) g_pnorm = sqrtf(sh[0]);
}

__global__ void k_score(const float* __restrict__ h, const float* __restrict__ p) {
    int w = (blockIdx.x * blockDim.x + threadIdx.x) >> 5;
    int lane = threadIdx.x & 31;
    if (w >= NN) return;
    const float4 hv = *(const float4*)(h + (size_t)w * DD + lane * 4);
    const float4 pv = *(const float4*)(p + lane * 4);
    float d = hv.x * pv.x + hv.y * pv.y + hv.z * pv.z + hv.w * pv.w;
    for (int o = 16; o; o >>= 1) d += __shfl_xor_sync(0xffffffffu, d, o);
    if (lane == 0) {
        float sc = d / g_pnorm;
        g_score[w] = sc;
        unsigned u = __float_as_uint(sc);
        unsigned key = (u & 0x80000000u) ? ~u : (u | 0x80000000u);
        g_key[w] = (g_maskf[w] > 0.f) ? key : 0u;
    }
}

__global__ void k_topk_init(unsigned k) {
    int t = threadIdx.x;
    if (t < 256) g_bins[t] = 0u;
    if (t == 0) { g_prefix = 0u; g_krem = k; }
}

__global__ void k_hist(int pass) {
    __shared__ unsigned hb[256];
    int t = threadIdx.x;
    if (t < 256) hb[t] = 0u;
    __syncthreads();
    unsigned pref = g_prefix;
    int shift = 24 - 8 * pass;
    for (int n = blockIdx.x * blockDim.x + t; n < NN; n += gridDim.x * blockDim.x) {
        unsigned key = g_key[n];
        bool ok = (pass == 0) || ((key >> (32 - 8 * pass)) == pref);
        if (ok) atomicAdd(&hb[(key >> shift) & 255u], 1u);
    }
    __syncthreads();
    if (t < 256 && hb[t]) atomicAdd(&g_bins[t], hb[t]);
}

__global__ void k_select() {   // 256 threads: parallel suffix-sum selection
    __shared__ unsigned s[256];
    int t = threadIdx.x;
    unsigned v = g_bins[t];
    unsigned krem = g_krem;
    s[t] = v;
    __syncthreads();
    for (int off = 1; off < 256; off <<= 1) {
        unsigned add = (t + off < 256) ? s[t + off] : 0u;
        __syncthreads();
        s[t] += add;
        __syncthreads();
    }
    unsigned suf = s[t];
    unsigned sufN = (t < 255) ? s[t + 1] : 0u;   // note: s[t+1] already final (monotone loop)
    if (suf >= krem && sufN < krem) {
        g_prefix = (g_prefix << 8) | (unsigned)t;
        g_krem = krem - sufN;
    }
    g_bins[t] = 0u;
}

__global__ void k_kept() {
    int n = blockIdx.x * blockDim.x + threadIdx.x;
    if (n < NN) {
        unsigned thr = g_prefix;
        float kept = (g_key[n] >= thr) ? 1.f : 0.f;
        g_maskf[n] = kept;
        g_scale[n] = (kept != 0.f) ? tanhf(g_score[n]) : 0.f;
        g_weights[n] = g_aggr[n] * kept;
    }
}

__global__ void k_scalex(const float* __restrict__ in, float* __restrict__ out) {
    int i = blockIdx.x * blockDim.x + threadIdx.x;
    if (i < NN * DD) out[i] = in[i] * g_scale[i >> 7];
}

// ---------------- host sequence ----------------
extern "C" void kernel_launch(void* const* d_in, const int* in_sizes, int n_in,
                              void* d_out, int out_size) {
    const float* x_in = (const float*)d_in[0];
    const int*   ei   = (const int*)d_in[1];
    const int*   row  = ei;
    const int*   col  = ei + EE;
    const float* Wd = (const float*)d_in[2];
    const float* bd = (const float*)d_in[3];
    const float* Wu = (const float*)d_in[4];
    const float* bu = (const float*)d_in[5];
    const float* Wb = (const float*)d_in[6];
    const float* bb = (const float*)d_in[7];
    const float* pv = (const float*)d_in[8];
    float* out = (float*)d_out;

    void *pt, *ph, *ph2, *px, *pd0, *pd1;
    void *pc0, *pc1, *pc2, *pec0, *pec1;
    void *pcolptr, *prowptr, *perowc, *peidc, *pecolr, *peidr;
    cudaGetSymbolAddress(&pt,  g_t);   cudaGetSymbolAddress(&ph,  g_h);
    cudaGetSymbolAddress(&ph2, g_h2);  cudaGetSymbolAddress(&px,  g_x);
    cudaGetSymbolAddress(&pd0, g_d0);  cudaGetSymbolAddress(&pd1, g_d1);
    cudaGetSymbolAddress(&pc0, g_c0);  cudaGetSymbolAddress(&pc1, g_c1);
    cudaGetSymbolAddress(&pc2, g_c2);  cudaGetSymbolAddress(&pec0, g_ec0);
    cudaGetSymbolAddress(&pec1, g_ec1);
    cudaGetSymbolAddress(&pcolptr, g_colptr); cudaGetSymbolAddress(&prowptr, g_rowptr);
    cudaGetSymbolAddress(&perowc, g_erow_c);  cudaGetSymbolAddress(&peidc,  g_eid_c);
    cudaGetSymbolAddress(&pecolr, g_ecol_r);  cudaGetSymbolAddress(&peidr,  g_eid_r);

    float *t = (float*)pt, *h = (float*)ph, *h2 = (float*)ph2, *x = (float*)px;
    float *d0 = (float*)pd0, *d1 = (float*)pd1;
    float *c0 = (float*)pc0, *c1 = (float*)pc1, *c2 = (float*)pc2;
    float *ec0 = (float*)pec0, *ec1 = (float*)pec1;
    int *colptr = (int*)pcolptr, *rowptr = (int*)prowptr;
    int *erowc = (int*)perowc, *eidc = (int*)peidc;
    int *ecolr = (int*)pecolr, *eidr = (int*)peidr;

    const int GN  = (NN + 255) / 256;        // 196
    const int GE  = (EE + 255) / 256;        // 3125
    const int GW  = (NN * 32 + 255) / 256;   // 6250  (warp per node)
    const int GND = (NN * DD + 255) / 256;   // 25000
    const int GG  = (NN + 127) / 128;        // 391   (tensor GEMM)

    // ---- setup: CSR build + level-0 norm ----
    k_init<<<GN, 256>>>();
    k_edge_hist<<<GE, 256>>>(row, col);
    k_bsum<<<GN, 256>>>();
    k_bscan<<<1, 256>>>(GN);
    k_scan3<<<GN, 256>>>();
    k_fill<<<GE, 256>>>(row, col);
    k_degdis<<<GW, 256>>>();
    k_coef<<<GE, 256>>>(row, col, c0);

    auto GCN = [&](const float* in, const float* W, const float* b,
                   const float* cf, const float* init, float* o) {
        k_gemm_tc<<<GG, 256>>>(in, W, b, t);
        k_spmm<<<GW, 256>>>(colptr, erowc, eidc, cf, t, init, o);
    };
    auto TOPK = [&](const float* hin, const float* p, unsigned k, float* xout) {
        k_pnorm<<<1, 128>>>(p);
        k_score<<<GW, 256>>>(hin, p);
        k_topk_init<<<1, 256>>>(k);
        for (int pass = 0; pass < 4; pass++) {
            k_hist<<<GN, 256>>>(pass);
            k_select<<<1, 256>>>();
        }
        k_kept<<<GN, 256>>>();
        k_scalex<<<GND, 256>>>(hin, xout);
    };

    // ---- down layer 0 ----
    GCN(x_in, Wd + 0 * DD * DD, bd + 0 * DD, c0, nullptr, h);
    GCN(h,    Wd + 1 * DD * DD, bd + 1 * DD, c0, nullptr, d0);
    k_aggr<<<GW, 256>>>();
    k_ec<<<GE, 256>>>(row, col, ec0);
    k_spmm<<<GW, 256>>>(colptr, erowc, eidc, ec0, d0, nullptr, h2);
    TOPK(h2, pv, 25000u, x);
    k_degdis<<<GW, 256>>>();
    k_coef<<<GE, 256>>>(row, col, c1);

    // ---- down layer 1 ----
    GCN(x, Wd + 2 * DD * DD, bd + 2 * DD, c1, nullptr, h);
    GCN(h, Wd + 3 * DD * DD, bd + 3 * DD, c1, nullptr, d1);
    k_aggr<<<GW, 256>>>();
    k_ec<<<GE, 256>>>(row, col, ec1);
    k_spmm<<<GW, 256>>>(colptr, erowc, eidc, ec1, d1, nullptr, h2);
    TOPK(h2, pv + DD, 12500u, x);
    k_degdis<<<GW, 256>>>();
    k_coef<<<GE, 256>>>(row, col, c2);

    // ---- bottom ----
    GCN(x, Wb + 0 * DD * DD, bb + 0 * DD, c2, nullptr, h);
    GCN(h, Wb + 1 * DD * DD, bb + 1 * DD, c2, nullptr, x);

    // ---- up layer 0 (level-1 masks; residual d1) ----
    k_spmm<<<GW, 256>>>(rowptr, ecolr, eidr, ec1, x, nullptr, h);
    GCN(h,  Wu + 0 * DD * DD, bu + 0 * DD, c1, nullptr, h2);
    GCN(h2, Wu + 1 * DD * DD, bu + 1 * DD, c1, d1, x);

    // ---- up layer 1 (level-0 masks; residual d0) -> final output ----
    k_spmm<<<GW, 256>>>(rowptr, ecolr, eidr, ec0, x, nullptr, h);
    GCN(h,  Wu + 2 * DD * DD, bu + 2 * DD, c0, nullptr, h2);
    GCN(h2, Wu + 3 * DD * DD, bu + 3 * DD, c0, d0, out);
}

// round 3
// speedup vs baseline: 1.2636x; 1.0725x over previous
#include <cuda_runtime.h>
#include <math.h>

#define NN 50000
#define DD 128
#define EE 800000

// ---------------- device scratch ----------------
__device__ __align__(16) float g_t [NN*DD];
__device__ __align__(16) float g_h [NN*DD];
__device__ __align__(16) float g_h2[NN*DD];
__device__ __align__(16) float g_x [NN*DD];
__device__ __align__(16) float g_d0[NN*DD];
__device__ __align__(16) float g_d1[NN*DD];

__device__ int g_cntc[NN], g_cntr[NN];
__device__ int g_colptr[NN+1], g_rowptr[NN+1];
__device__ int g_nextc[NN], g_nextr[NN];
__device__ int g_erow_c[EE];   // col-CSR: neighbor = row endpoint
__device__ int g_ecol_r[EE];   // row-CSR: neighbor = col endpoint

__device__ int g_bsc[256], g_bsr[256], g_boc[256], g_bor[256];

__device__ float g_dis0[NN], g_dis1[NN], g_dis2[NN];
__device__ float g_s0[NN], g_s1[NN], g_s2[NN];
__device__ float g_r0[NN], g_r1[NN];
__device__ float g_maskf[NN], g_weights[NN], g_aggr[NN];
__device__ float g_score[NN];
__device__ unsigned g_key[NN];
__device__ unsigned g_bins[256];
__device__ unsigned g_prefix, g_krem;
__device__ float g_pnorm;

// ---------------- setup ----------------
__global__ void k_init() {
    int i = blockIdx.x * blockDim.x + threadIdx.x;
    if (i < NN) { g_cntc[i] = 0; g_cntr[i] = 0; g_maskf[i] = 1.f; g_weights[i] = 1.f; }
}

__global__ void k_edge_hist(const int* __restrict__ row, const int* __restrict__ col) {
    int e = blockIdx.x * blockDim.x + threadIdx.x;
    if (e < EE) { atomicAdd(&g_cntc[col[e]], 1); atomicAdd(&g_cntr[row[e]], 1); }
}

__global__ void k_bsum() {
    __shared__ int sc[8], sr[8];
    int t = threadIdx.x;
    int i = blockIdx.x * 256 + t;
    int vc = (i < NN) ? g_cntc[i] : 0;
    int vr = (i < NN) ? g_cntr[i] : 0;
    for (int o = 16; o; o >>= 1) {
        vc += __shfl_xor_sync(0xffffffffu, vc, o);
        vr += __shfl_xor_sync(0xffffffffu, vr, o);
    }
    if ((t & 31) == 0) { sc[t >> 5] = vc; sr[t >> 5] = vr; }
    __syncthreads();
    if (t == 0) {
        int ac = 0, ar = 0;
        for (int w = 0; w < 8; w++) { ac += sc[w]; ar += sr[w]; }
        g_bsc[blockIdx.x] = ac; g_bsr[blockIdx.x] = ar;
    }
}

__global__ void k_bscan(int nblk) {
    __shared__ int s1[8], s2[8];
    int t = threadIdx.x, lane = t & 31, w = t >> 5;
    int vc = (t < nblk) ? g_bsc[t] : 0;
    int vr = (t < nblk) ? g_bsr[t] : 0;
    int ic = vc, ir = vr;
    for (int o = 1; o < 32; o <<= 1) {
        int nc = __shfl_up_sync(0xffffffffu, ic, o);
        int nr = __shfl_up_sync(0xffffffffu, ir, o);
        if (lane >= o) { ic += nc; ir += nr; }
    }
    if (lane == 31) { s1[w] = ic; s2[w] = ir; }
    __syncthreads();
    if (w == 0) {
        int a = (lane < 8) ? s1[lane] : 0;
        int b = (lane < 8) ? s2[lane] : 0;
        for (int o = 1; o < 8; o <<= 1) {
            int na = __shfl_up_sync(0xffffffffu, a, o);
            int nb = __shfl_up_sync(0xffffffffu, b, o);
            if (lane >= o) { a += na; b += nb; }
        }
        if (lane < 8) { s1[lane] = a; s2[lane] = b; }
    }
    __syncthreads();
    int offc = (w == 0) ? 0 : s1[w - 1];
    int offr = (w == 0) ? 0 : s2[w - 1];
    if (t < nblk) { g_boc[t] = offc + ic - vc; g_bor[t] = offr + ir - vr; }
}

__device__ __forceinline__ int blk_exscan(int v, int* ws) {
    __syncthreads();
    int lane = threadIdx.x & 31, w = threadIdx.x >> 5;
    int inc = v;
    for (int o = 1; o < 32; o <<= 1) {
        int n = __shfl_up_sync(0xffffffffu, inc, o);
        if (lane >= o) inc += n;
    }
    if (lane == 31) ws[w] = inc;
    __syncthreads();
    if (w == 0) {
        int s = (lane < 8) ? ws[lane] : 0;
        for (int o = 1; o < 8; o <<= 1) {
            int n = __shfl_up_sync(0xffffffffu, s, o);
            if (lane >= o) s += n;
        }
        if (lane < 8) ws[lane] = s;
    }
    __syncthreads();
    int woff = (w == 0) ? 0 : ws[w - 1];
    return woff + inc - v;
}

__global__ void k_scan3() {
    __shared__ int ws[8];
    int t = threadIdx.x;
    int i = blockIdx.x * 256 + t;
    int vc = (i < NN) ? g_cntc[i] : 0;
    int vr = (i < NN) ? g_cntr[i] : 0;
    int exc = blk_exscan(vc, ws);
    int exr = blk_exscan(vr, ws);
    if (i < NN) {
        int pc = g_boc[blockIdx.x] + exc; g_colptr[i] = pc; g_nextc[i] = pc;
        int pr = g_bor[blockIdx.x] + exr; g_rowptr[i] = pr; g_nextr[i] = pr;
    }
    if (i == 0) { g_colptr[NN] = EE; g_rowptr[NN] = EE; }
}

__global__ void k_fill(const int* __restrict__ row, const int* __restrict__ col) {
    int e = blockIdx.x * blockDim.x + threadIdx.x;
    if (e < EE) {
        int r = row[e], c = col[e];
        int p = atomicAdd(&g_nextc[c], 1); g_erow_c[p] = r;
        int q = atomicAdd(&g_nextr[r], 1); g_ecol_r[q] = c;
    }
}

// deg over active out-edges (row-CSR) -> dis = deg^-1/2, s = weights/deg
__global__ void k_degdis(float* __restrict__ dis_out, float* __restrict__ s_out) {
    int w = (blockIdx.x * blockDim.x + threadIdx.x) >> 5;
    int lane = threadIdx.x & 31;
    if (w >= NN) return;
    float mw = g_maskf[w];
    if (mw == 0.f) {
        if (lane == 0) { dis_out[w] = 0.f; s_out[w] = 0.f; }
        return;
    }
    int s0 = g_rowptr[w], e0 = g_rowptr[w + 1];
    float sum = 0.f;
    for (int j = s0 + lane; j < e0; j += 32) sum += g_maskf[g_ecol_r[j]];
    for (int o = 16; o; o >>= 1) sum += __shfl_xor_sync(0xffffffffu, sum, o);
    if (lane == 0) {
        float deg = sum;   // mw == 1
        dis_out[w] = (deg > 0.f) ? rsqrtf(deg) : 0.f;
        s_out[w]   = (deg > 0.f) ? g_weights[w] / deg : 0.f;
    }
}

// ---------------- tensor-core GEMM (3xTF32): out = X @ W + b ----------------
__device__ __forceinline__ float f2tf(float a) {
    unsigned u;
    asm("cvt.rna.tf32.f32 %0, %1;" : "=r"(u) : "f"(a));
    return __uint_as_float(u);
}

__device__ __forceinline__ void mma_tf32(float* d, const unsigned* a, unsigned b0, unsigned b1) {
    asm volatile(
        "mma.sync.aligned.m16n8k8.row.col.f32.tf32.tf32.f32 "
        "{%0,%1,%2,%3}, {%4,%5,%6,%7}, {%8,%9}, {%0,%1,%2,%3};"
        : "+f"(d[0]), "+f"(d[1]), "+f"(d[2]), "+f"(d[3])
        : "r"(a[0]), "r"(a[1]), "r"(a[2]), "r"(a[3]), "r"(b0), "r"(b1));
}

__global__ void __launch_bounds__(256, 1)
k_gemm_tc(const float* __restrict__ X, const float* __restrict__ W,
          const float* __restrict__ bias, float* __restrict__ out) {
    __shared__ __align__(16) float As[2][128][20];
    __shared__ __align__(16) float Bs[2][16][132];
    int tid  = threadIdx.x;
    int lane = tid & 31;
    int warp = tid >> 5;
    int wm = warp & 3;
    int wn = warp >> 2;
    int gid = lane >> 2;
    int tig = lane & 3;
    int row0 = blockIdx.x * 128;

    float acc[2][8][4];
#pragma unroll
    for (int mt = 0; mt < 2; mt++)
#pragma unroll
        for (int nt = 0; nt < 8; nt++)
#pragma unroll
            for (int q = 0; q < 4; q++) acc[mt][nt][q] = 0.f;

    for (int kb = 0; kb < 8; kb++) {
#pragma unroll
        for (int ii = 0; ii < 2; ii++) {
            int i = tid + ii * 256;
            int r = i >> 2, c4 = i & 3;
            int gr = row0 + r;
            float4 v = make_float4(0.f, 0.f, 0.f, 0.f);
            if (gr < NN) v = *(const float4*)(X + (size_t)gr * 128 + kb * 16 + c4 * 4);
            float4 hi, lo;
            hi.x = f2tf(v.x); lo.x = f2tf(v.x - hi.x);
            hi.y = f2tf(v.y); lo.y = f2tf(v.y - hi.y);
            hi.z = f2tf(v.z); lo.z = f2tf(v.z - hi.z);
            hi.w = f2tf(v.w); lo.w = f2tf(v.w - hi.w);
            *(float4*)&As[0][r][c4 * 4] = hi;
            *(float4*)&As[1][r][c4 * 4] = lo;
        }
#pragma unroll
        for (int ii = 0; ii < 2; ii++) {
            int i = tid + ii * 256;
            int r = i >> 5, c4 = i & 31;
            float4 v = *(const float4*)(W + (size_t)(kb * 16 + r) * 128 + c4 * 4);
            float4 hi, lo;
            hi.x = f2tf(v.x); lo.x = f2tf(v.x - hi.x);
            hi.y = f2tf(v.y); lo.y = f2tf(v.y - hi.y);
            hi.z = f2tf(v.z); lo.z = f2tf(v.z - hi.z);
            hi.w = f2tf(v.w); lo.w = f2tf(v.w - hi.w);
            *(float4*)&Bs[0][r][c4 * 4] = hi;
            *(float4*)&Bs[1][r][c4 * 4] = lo;
        }
        __syncthreads();

#pragma unroll
        for (int ks = 0; ks < 2; ks++) {
            int k0 = ks * 8;
            unsigned ah[2][4], al[2][4];
#pragma unroll
            for (int mt = 0; mt < 2; mt++) {
                int r = wm * 32 + mt * 16 + gid;
                int c = k0 + tig;
                ah[mt][0] = __float_as_uint(As[0][r][c]);
                ah[mt][1] = __float_as_uint(As[0][r + 8][c]);
                ah[mt][2] = __float_as_uint(As[0][r][c + 4]);
                ah[mt][3] = __float_as_uint(As[0][r + 8][c + 4]);
                al[mt][0] = __float_as_uint(As[1][r][c]);
                al[mt][1] = __float_as_uint(As[1][r + 8][c]);
                al[mt][2] = __float_as_uint(As[1][r][c + 4]);
                al[mt][3] = __float_as_uint(As[1][r + 8][c + 4]);
            }
#pragma unroll
            for (int nt = 0; nt < 8; nt++) {
                int kk = k0 + tig;
                int nn0 = wn * 64 + nt * 8 + gid;
                unsigned bh0 = __float_as_uint(Bs[0][kk][nn0]);
                unsigned bh1 = __float_as_uint(Bs[0][kk + 4][nn0]);
                unsigned bl0 = __float_as_uint(Bs[1][kk][nn0]);
                unsigned bl1 = __float_as_uint(Bs[1][kk + 4][nn0]);
#pragma unroll
                for (int mt = 0; mt < 2; mt++) {
                    mma_tf32(acc[mt][nt], ah[mt], bh0, bh1);
                    mma_tf32(acc[mt][nt], ah[mt], bl0, bl1);
                    mma_tf32(acc[mt][nt], al[mt], bh0, bh1);
                }
            }
        }
        __syncthreads();
    }

#pragma unroll
    for (int nt = 0; nt < 8; nt++) {
        int c = wn * 64 + nt * 8 + tig * 2;
        float b0 = __ldg(bias + c), b1 = __ldg(bias + c + 1);
#pragma unroll
        for (int mt = 0; mt < 2; mt++) {
            int r = row0 + wm * 32 + mt * 16 + gid;
            if (r < NN) {
                float2 o0 = make_float2(acc[mt][nt][0] + b0, acc[mt][nt][1] + b1);
                *(float2*)(out + (size_t)r * 128 + c) = o0;
            }
            if (r + 8 < NN) {
                float2 o1 = make_float2(acc[mt][nt][2] + b0, acc[mt][nt][3] + b1);
                *(float2*)(out + (size_t)(r + 8) * 128 + c) = o1;
            }
        }
    }
}

// ---------- GCN SpMM: out[w] = init[w] + dis[w] * sum_j dis[nbr]*in[nbr] ----------
__global__ void k_spmm_gcn(const int* __restrict__ ptr, const int* __restrict__ nbr,
                           const float* __restrict__ dis,
                           const float* __restrict__ in, const float* __restrict__ init,
                           float* __restrict__ out) {
    int w = (blockIdx.x * blockDim.x + threadIdx.x) >> 5;
    int lane = threadIdx.x & 31;
    if (w >= NN) return;
    float4 acc;
    if (init) acc = *(const float4*)(init + (size_t)w * DD + lane * 4);
    else      acc = make_float4(0.f, 0.f, 0.f, 0.f);
    float dw = dis[w];
    if (dw != 0.f) {
        int s0 = ptr[w], e0 = ptr[w + 1];
        float4 sum = make_float4(0.f, 0.f, 0.f, 0.f);
        for (int j = s0; j < e0; j++) {
            int n = nbr[j];
            float c = dis[n];        // same addr across lanes -> broadcast
            if (c != 0.f) {
                const float4 v = *(const float4*)(in + (size_t)n * DD + lane * 4);
                sum.x = fmaf(c, v.x, sum.x);
                sum.y = fmaf(c, v.y, sum.y);
                sum.z = fmaf(c, v.z, sum.z);
                sum.w = fmaf(c, v.w, sum.w);
            }
        }
        acc.x = fmaf(dw, sum.x, acc.x);
        acc.y = fmaf(dw, sum.y, acc.y);
        acc.z = fmaf(dw, sum.z, acc.z);
        acc.w = fmaf(dw, sum.w, acc.w);
    }
    *(float4*)(out + (size_t)w * DD + lane * 4) = acc;
}

// ---------- down WEC fused: aggr + h2 + r + score/key (col-CSR) ----------
__global__ void k_wec_down(const float* __restrict__ s, const float* __restrict__ in,
                           const float* __restrict__ p,
                           float* __restrict__ out, float* __restrict__ r_out) {
    int w = (blockIdx.x * blockDim.x + threadIdx.x) >> 5;
    int lane = threadIdx.x & 31;
    if (w >= NN) return;
    float mw = g_maskf[w];
    float4 acc = make_float4(0.f, 0.f, 0.f, 0.f);
    if (mw > 0.f) {
        int s0 = g_colptr[w], e0 = g_colptr[w + 1];
        // pass 1: aggr = sum s[nbr] (strided + full-warp reduce)
        float ss = 0.f;
        for (int j = s0 + lane; j < e0; j += 32) ss += s[g_erow_c[j]];
        for (int o = 16; o; o >>= 1) ss += __shfl_xor_sync(0xffffffffu, ss, o);
        float aggr = ss + 1e-12f;
        float inv = 1.f / aggr;
        if (lane == 0) { g_aggr[w] = aggr; r_out[w] = inv; }
        // pass 2: weighted row sum
        float4 sum = make_float4(0.f, 0.f, 0.f, 0.f);
        for (int j = s0; j < e0; j++) {
            int n = g_erow_c[j];
            float c = s[n];
            if (c != 0.f) {
                const float4 v = *(const float4*)(in + (size_t)n * DD + lane * 4);
                sum.x = fmaf(c, v.x, sum.x);
                sum.y = fmaf(c, v.y, sum.y);
                sum.z = fmaf(c, v.z, sum.z);
                sum.w = fmaf(c, v.w, sum.w);
            }
        }
        acc.x = inv * sum.x; acc.y = inv * sum.y;
        acc.z = inv * sum.z; acc.w = inv * sum.w;
    } else if (lane == 0) {
        r_out[w] = 0.f;
    }
    *(float4*)(out + (size_t)w * DD + lane * 4) = acc;
    // fused score: d = <acc, p_lane> reduced over warp
    const float4 pv = *(const float4*)(p + lane * 4);
    float d = acc.x * pv.x + acc.y * pv.y + acc.z * pv.z + acc.w * pv.w;
    for (int o = 16; o; o >>= 1) d += __shfl_xor_sync(0xffffffffu, d, o);
    if (lane == 0) {
        float sc = d / g_pnorm;
        g_score[w] = sc;
        unsigned u = __float_as_uint(sc);
        unsigned key = (u & 0x80000000u) ? ~u : (u | 0x80000000u);
        g_key[w] = (mw > 0.f) ? key : 0u;
    }
}

// ---------- up WEC: out[w] = s[w] * sum_j r[nbr]*x[nbr]  (row-CSR) ----------
__global__ void k_wec_up(const float* __restrict__ s, const float* __restrict__ r,
                         const float* __restrict__ in, float* __restrict__ out) {
    int w = (blockIdx.x * blockDim.x + threadIdx.x) >> 5;
    int lane = threadIdx.x & 31;
    if (w >= NN) return;
    float sw = s[w];
    float4 acc = make_float4(0.f, 0.f, 0.f, 0.f);
    if (sw != 0.f) {
        int s0 = g_rowptr[w], e0 = g_rowptr[w + 1];
        float4 sum = make_float4(0.f, 0.f, 0.f, 0.f);
        for (int j = s0; j < e0; j++) {
            int n = g_ecol_r[j];
            float c = r[n];
            if (c != 0.f) {
                const float4 v = *(const float4*)(in + (size_t)n * DD + lane * 4);
                sum.x = fmaf(c, v.x, sum.x);
                sum.y = fmaf(c, v.y, sum.y);
                sum.z = fmaf(c, v.z, sum.z);
                sum.w = fmaf(c, v.w, sum.w);
            }
        }
        acc.x = sw * sum.x; acc.y = sw * sum.y;
        acc.z = sw * sum.z; acc.w = sw * sum.w;
    }
    *(float4*)(out + (size_t)w * DD + lane * 4) = acc;
}

// ---------------- top-k ----------------
__global__ void k_pnorm(const float* __restrict__ p) {
    __shared__ float sh[128];
    int t = threadIdx.x;
    float v = p[t];
    sh[t] = v * v;
    __syncthreads();
    for (int o = 64; o; o >>= 1) { if (t < o) sh[t] += sh[t + o]; __syncthreads(); }
    if (t == 0) g_pnorm = sqrtf(sh[0]);
}

__global__ void k_topk_init(unsigned k) {
    int t = threadIdx.x;
    if (t < 256) g_bins[t] = 0u;
    if (t == 0) { g_prefix = 0u; g_krem = k; }
}

__global__ void k_hist(int pass) {
    __shared__ unsigned hb[256];
    int t = threadIdx.x;
    if (t < 256) hb[t] = 0u;
    __syncthreads();
    unsigned pref = g_prefix;
    int shift = 24 - 8 * pass;
    for (int n = blockIdx.x * blockDim.x + t; n < NN; n += gridDim.x * blockDim.x) {
        unsigned key = g_key[n];
        bool ok = (pass == 0) || ((key >> (32 - 8 * pass)) == pref);
        if (ok) atomicAdd(&hb[(key >> shift) & 255u], 1u);
    }
    __syncthreads();
    if (t < 256 && hb[t]) atomicAdd(&g_bins[t], hb[t]);
}

__global__ void k_select() {
    __shared__ unsigned s[256];
    int t = threadIdx.x;
    unsigned v = g_bins[t];
    unsigned krem = g_krem;
    s[t] = v;
    __syncthreads();
    for (int off = 1; off < 256; off <<= 1) {
        unsigned add = (t + off < 256) ? s[t + off] : 0u;
        __syncthreads();
        s[t] += add;
        __syncthreads();
    }
    unsigned suf = s[t];
    unsigned sufN = (t < 255) ? s[t + 1] : 0u;
    if (suf >= krem && sufN < krem) {
        g_prefix = (g_prefix << 8) | (unsigned)t;
        g_krem = krem - sufN;
    }
    g_bins[t] = 0u;
}

// fused kept + weights + mask + scale-x (warp per node)
__global__ void k_keptscale(const float* __restrict__ in, float* __restrict__ out) {
    int w = (blockIdx.x * blockDim.x + threadIdx.x) >> 5;
    int lane = threadIdx.x & 31;
    if (w >= NN) return;
    float scale = 0.f;
    if (lane == 0) {
        unsigned thr = g_prefix;
        float kept = (g_key[w] >= thr) ? 1.f : 0.f;
        g_maskf[w] = kept;
        g_weights[w] = g_aggr[w] * kept;
        scale = (kept != 0.f) ? tanhf(g_score[w]) : 0.f;
    }
    scale = __shfl_sync(0xffffffffu, scale, 0);
    float4 v = *(const float4*)(in + (size_t)w * DD + lane * 4);
    v.x *= scale; v.y *= scale; v.z *= scale; v.w *= scale;
    *(float4*)(out + (size_t)w * DD + lane * 4) = v;
}

// ---------------- host sequence ----------------
extern "C" void kernel_launch(void* const* d_in, const int* in_sizes, int n_in,
                              void* d_out, int out_size) {
    const float* x_in = (const float*)d_in[0];
    const int*   ei   = (const int*)d_in[1];
    const int*   row  = ei;
    const int*   col  = ei + EE;
    const float* Wd = (const float*)d_in[2];
    const float* bd = (const float*)d_in[3];
    const float* Wu = (const float*)d_in[4];
    const float* bu = (const float*)d_in[5];
    const float* Wb = (const float*)d_in[6];
    const float* bb = (const float*)d_in[7];
    const float* pv = (const float*)d_in[8];
    float* out = (float*)d_out;

    void *pt, *ph, *ph2, *px, *pd0, *pd1;
    void *pcolptr, *prowptr, *perowc, *pecolr;
    void *pdis0, *pdis1, *pdis2, *ps0, *ps1, *ps2, *pr0, *pr1;
    cudaGetSymbolAddress(&pt,  g_t);   cudaGetSymbolAddress(&ph,  g_h);
    cudaGetSymbolAddress(&ph2, g_h2);  cudaGetSymbolAddress(&px,  g_x);
    cudaGetSymbolAddress(&pd0, g_d0);  cudaGetSymbolAddress(&pd1, g_d1);
    cudaGetSymbolAddress(&pcolptr, g_colptr); cudaGetSymbolAddress(&prowptr, g_rowptr);
    cudaGetSymbolAddress(&perowc, g_erow_c);  cudaGetSymbolAddress(&pecolr, g_ecol_r);
    cudaGetSymbolAddress(&pdis0, g_dis0); cudaGetSymbolAddress(&pdis1, g_dis1);
    cudaGetSymbolAddress(&pdis2, g_dis2);
    cudaGetSymbolAddress(&ps0, g_s0); cudaGetSymbolAddress(&ps1, g_s1);
    cudaGetSymbolAddress(&ps2, g_s2);
    cudaGetSymbolAddress(&pr0, g_r0); cudaGetSymbolAddress(&pr1, g_r1);

    float *t = (float*)pt, *h = (float*)ph, *h2 = (float*)ph2, *x = (float*)px;
    float *d0 = (float*)pd0, *d1 = (float*)pd1;
    int *colptr = (int*)pcolptr, *rowptr = (int*)prowptr;
    int *erowc = (int*)perowc, *ecolr = (int*)pecolr;
    float *dis0 = (float*)pdis0, *dis1 = (float*)pdis1, *dis2 = (float*)pdis2;
    float *s0 = (float*)ps0, *s1 = (float*)ps1, *s2 = (float*)ps2;
    float *r0 = (float*)pr0, *r1 = (float*)pr1;

    const int GN = (NN + 255) / 256;       // 196
    const int GE = (EE + 255) / 256;       // 3125
    const int GW = (NN * 32 + 255) / 256;  // 6250 (warp per node)
    const int GG = (NN + 127) / 128;       // 391

    // ---- setup ----
    k_init<<<GN, 256>>>();
    k_edge_hist<<<GE, 256>>>(row, col);
    k_bsum<<<GN, 256>>>();
    k_bscan<<<1, 256>>>(GN);
    k_scan3<<<GN, 256>>>();
    k_fill<<<GE, 256>>>(row, col);

    auto GCN = [&](const float* in, const float* W, const float* b,
                   const float* dis, const float* init, float* o) {
        k_gemm_tc<<<GG, 256>>>(in, W, b, t);
        k_spmm_gcn<<<GW, 256>>>(colptr, erowc, dis, t, init, o);
    };
    auto TOPK = [&](unsigned k, const float* hin, float* xout) {
        k_topk_init<<<1, 256>>>(k);
        for (int pass = 0; pass < 4; pass++) {
            k_hist<<<GN, 256>>>(pass);
            k_select<<<1, 256>>>();
        }
        k_keptscale<<<GW, 256>>>(hin, xout);
    };

    // ---- down layer 0 ----
    k_degdis<<<GW, 256>>>(dis0, s0);
    k_pnorm<<<1, 128>>>(pv);
    GCN(x_in, Wd + 0 * DD * DD, bd + 0 * DD, dis0, nullptr, h);
    GCN(h,    Wd + 1 * DD * DD, bd + 1 * DD, dis0, nullptr, d0);
    k_wec_down<<<GW, 256>>>(s0, d0, pv, h2, r0);
    TOPK(25000u, h2, x);

    // ---- down layer 1 ----
    k_degdis<<<GW, 256>>>(dis1, s1);
    k_pnorm<<<1, 128>>>(pv + DD);
    GCN(x, Wd + 2 * DD * DD, bd + 2 * DD, dis1, nullptr, h);
    GCN(h, Wd + 3 * DD * DD, bd + 3 * DD, dis1, nullptr, d1);
    k_wec_down<<<GW, 256>>>(s1, d1, pv + DD, h2, r1);
    TOPK(12500u, h2, x);

    // ---- bottom ----
    k_degdis<<<GW, 256>>>(dis2, s2);
    GCN(x, Wb + 0 * DD * DD, bb + 0 * DD, dis2, nullptr, h);
    GCN(h, Wb + 1 * DD * DD, bb + 1 * DD, dis2, nullptr, x);

    // ---- up layer 0 (level-1 masks; residual d1) ----
    k_wec_up<<<GW, 256>>>(s1, r1, x, h);
    GCN(h,  Wu + 0 * DD * DD, bu + 0 * DD, dis1, nullptr, h2);
    GCN(h2, Wu + 1 * DD * DD, bu + 1 * DD, dis1, d1, x);

    // ---- up layer 1 (level-0 masks; residual d0) -> output ----
    k_wec_up<<<GW, 256>>>(s0, r0, x, h);
    GCN(h,  Wu + 2 * DD * DD, bu + 2 * DD, dis0, nullptr, h2);
    GCN(h2, Wu + 3 * DD * DD, bu + 3 * DD, dis0, d0, out);
}

// round 5
// speedup vs baseline: 1.3779x; 1.0905x over previous
#include <cuda_runtime.h>
#include <math.h>

#define NN 50000
#define DD 128
#define EE 800000

// ---------------- device scratch ----------------
__device__ __align__(16) float g_t [NN*DD];
__device__ __align__(16) float g_h [NN*DD];
__device__ __align__(16) float g_h2[NN*DD];
__device__ __align__(16) float g_x [NN*DD];
__device__ __align__(16) float g_d0[NN*DD];
__device__ __align__(16) float g_d1[NN*DD];

__device__ int g_cntc[NN], g_cntr[NN];
__device__ int g_colptr[NN+1], g_rowptr[NN+1];
__device__ int g_nextc[NN], g_nextr[NN];
__device__ int g_erow_c[EE];   // col-CSR: neighbor = row endpoint
__device__ int g_ecol_r[EE];   // row-CSR: neighbor = col endpoint

__device__ int g_bsc[256], g_bsr[256], g_boc[256], g_bor[256];

__device__ float g_dis0[NN], g_dis1[NN], g_dis2[NN];
__device__ float g_s0[NN], g_s1[NN], g_s2[NN];
__device__ float g_r0[NN], g_r1[NN];
__device__ float g_maskf[NN], g_weights[NN], g_aggr[NN];
__device__ float g_score[NN];
__device__ unsigned g_key[NN];
__device__ unsigned g_bins[256];
__device__ unsigned g_prefix, g_krem;
__device__ float g_pnorm;

// ---------------- setup ----------------
__global__ void k_init() {
    int i = blockIdx.x * blockDim.x + threadIdx.x;
    if (i < NN) { g_cntc[i] = 0; g_cntr[i] = 0; g_maskf[i] = 1.f; g_weights[i] = 1.f; }
}

__global__ void k_edge_hist(const int* __restrict__ row, const int* __restrict__ col) {
    int e = blockIdx.x * blockDim.x + threadIdx.x;
    if (e < EE) { atomicAdd(&g_cntc[col[e]], 1); atomicAdd(&g_cntr[row[e]], 1); }
}

__global__ void k_bsum() {
    __shared__ int sc[8], sr[8];
    int t = threadIdx.x;
    int i = blockIdx.x * 256 + t;
    int vc = (i < NN) ? g_cntc[i] : 0;
    int vr = (i < NN) ? g_cntr[i] : 0;
    for (int o = 16; o; o >>= 1) {
        vc += __shfl_xor_sync(0xffffffffu, vc, o);
        vr += __shfl_xor_sync(0xffffffffu, vr, o);
    }
    if ((t & 31) == 0) { sc[t >> 5] = vc; sr[t >> 5] = vr; }
    __syncthreads();
    if (t == 0) {
        int ac = 0, ar = 0;
        for (int w = 0; w < 8; w++) { ac += sc[w]; ar += sr[w]; }
        g_bsc[blockIdx.x] = ac; g_bsr[blockIdx.x] = ar;
    }
}

__global__ void k_bscan(int nblk) {
    __shared__ int s1[8], s2[8];
    int t = threadIdx.x, lane = t & 31, w = t >> 5;
    int vc = (t < nblk) ? g_bsc[t] : 0;
    int vr = (t < nblk) ? g_bsr[t] : 0;
    int ic = vc, ir = vr;
    for (int o = 1; o < 32; o <<= 1) {
        int nc = __shfl_up_sync(0xffffffffu, ic, o);
        int nr = __shfl_up_sync(0xffffffffu, ir, o);
        if (lane >= o) { ic += nc; ir += nr; }
    }
    if (lane == 31) { s1[w] = ic; s2[w] = ir; }
    __syncthreads();
    if (w == 0) {
        int a = (lane < 8) ? s1[lane] : 0;
        int b = (lane < 8) ? s2[lane] : 0;
        for (int o = 1; o < 8; o <<= 1) {
            int na = __shfl_up_sync(0xffffffffu, a, o);
            int nb = __shfl_up_sync(0xffffffffu, b, o);
            if (lane >= o) { a += na; b += nb; }
        }
        if (lane < 8) { s1[lane] = a; s2[lane] = b; }
    }
    __syncthreads();
    int offc = (w == 0) ? 0 : s1[w - 1];
    int offr = (w == 0) ? 0 : s2[w - 1];
    if (t < nblk) { g_boc[t] = offc + ic - vc; g_bor[t] = offr + ir - vr; }
}

__device__ __forceinline__ int blk_exscan(int v, int* ws) {
    __syncthreads();
    int lane = threadIdx.x & 31, w = threadIdx.x >> 5;
    int inc = v;
    for (int o = 1; o < 32; o <<= 1) {
        int n = __shfl_up_sync(0xffffffffu, inc, o);
        if (lane >= o) inc += n;
    }
    if (lane == 31) ws[w] = inc;
    __syncthreads();
    if (w == 0) {
        int s = (lane < 8) ? ws[lane] : 0;
        for (int o = 1; o < 8; o <<= 1) {
            int n = __shfl_up_sync(0xffffffffu, s, o);
            if (lane >= o) s += n;
        }
        if (lane < 8) ws[lane] = s;
    }
    __syncthreads();
    int woff = (w == 0) ? 0 : ws[w - 1];
    return woff + inc - v;
}

__global__ void k_scan3() {
    __shared__ int ws[8];
    int t = threadIdx.x;
    int i = blockIdx.x * 256 + t;
    int vc = (i < NN) ? g_cntc[i] : 0;
    int vr = (i < NN) ? g_cntr[i] : 0;
    int exc = blk_exscan(vc, ws);
    int exr = blk_exscan(vr, ws);
    if (i < NN) {
        int pc = g_boc[blockIdx.x] + exc; g_colptr[i] = pc; g_nextc[i] = pc;
        int pr = g_bor[blockIdx.x] + exr; g_rowptr[i] = pr; g_nextr[i] = pr;
    }
    if (i == 0) { g_colptr[NN] = EE; g_rowptr[NN] = EE; }
}

__global__ void k_fill(const int* __restrict__ row, const int* __restrict__ col) {
    int e = blockIdx.x * blockDim.x + threadIdx.x;
    if (e < EE) {
        int r = row[e], c = col[e];
        int p = atomicAdd(&g_nextc[c], 1); g_erow_c[p] = r;
        int q = atomicAdd(&g_nextr[r], 1); g_ecol_r[q] = c;
    }
}

// level-0 closed form: mask all ones -> deg = out-degree
__global__ void k_degdis0(float* __restrict__ dis_out, float* __restrict__ s_out) {
    int w = blockIdx.x * blockDim.x + threadIdx.x;
    if (w >= NN) return;
    float deg = (float)(g_rowptr[w + 1] - g_rowptr[w]);
    dis_out[w] = (deg > 0.f) ? rsqrtf(deg) : 0.f;
    s_out[w]   = (deg > 0.f) ? 1.f / deg : 0.f;
}

// general: deg over active out-edges (row-CSR)
__global__ void k_degdis(float* __restrict__ dis_out, float* __restrict__ s_out) {
    int w = (blockIdx.x * blockDim.x + threadIdx.x) >> 5;
    int lane = threadIdx.x & 31;
    if (w >= NN) return;
    float mw = g_maskf[w];
    if (mw == 0.f) {
        if (lane == 0) { dis_out[w] = 0.f; s_out[w] = 0.f; }
        return;
    }
    int s0 = g_rowptr[w], e0 = g_rowptr[w + 1];
    float sum = 0.f;
    for (int j = s0 + lane; j < e0; j += 32) sum += g_maskf[g_ecol_r[j]];
    for (int o = 16; o; o >>= 1) sum += __shfl_xor_sync(0xffffffffu, sum, o);
    if (lane == 0) {
        float deg = sum;
        dis_out[w] = (deg > 0.f) ? rsqrtf(deg) : 0.f;
        s_out[w]   = (deg > 0.f) ? g_weights[w] / deg : 0.f;
    }
}

// ---------------- tensor-core GEMM (3xTF32) ----------------
__device__ __forceinline__ float f2tf(float a) {
    unsigned u;
    asm("cvt.rna.tf32.f32 %0, %1;" : "=r"(u) : "f"(a));
    return __uint_as_float(u);
}

__device__ __forceinline__ void mma_tf32(float* d, const unsigned* a, unsigned b0, unsigned b1) {
    asm volatile(
        "mma.sync.aligned.m16n8k8.row.col.f32.tf32.tf32.f32 "
        "{%0,%1,%2,%3}, {%4,%5,%6,%7}, {%8,%9}, {%0,%1,%2,%3};"
        : "+f"(d[0]), "+f"(d[1]), "+f"(d[2]), "+f"(d[3])
        : "r"(a[0]), "r"(a[1]), "r"(a[2]), "r"(a[3]), "r"(b0), "r"(b1));
}

__global__ void __launch_bounds__(256, 1)
k_gemm_tc(const float* __restrict__ X, const float* __restrict__ W,
          const float* __restrict__ bias, float* __restrict__ out) {
    __shared__ __align__(16) float As[2][128][20];
    __shared__ __align__(16) float Bs[2][16][132];
    int tid  = threadIdx.x;
    int lane = tid & 31;
    int warp = tid >> 5;
    int wm = warp & 3;
    int wn = warp >> 2;
    int gid = lane >> 2;
    int tig = lane & 3;
    int row0 = blockIdx.x * 128;

    float acc[2][8][4];
#pragma unroll
    for (int mt = 0; mt < 2; mt++)
#pragma unroll
        for (int nt = 0; nt < 8; nt++)
#pragma unroll
            for (int q = 0; q < 4; q++) acc[mt][nt][q] = 0.f;

    for (int kb = 0; kb < 8; kb++) {
#pragma unroll
        for (int ii = 0; ii < 2; ii++) {
            int i = tid + ii * 256;
            int r = i >> 2, c4 = i & 3;
            int gr = row0 + r;
            float4 v = make_float4(0.f, 0.f, 0.f, 0.f);
            if (gr < NN) v = *(const float4*)(X + (size_t)gr * 128 + kb * 16 + c4 * 4);
            float4 hi, lo;
            hi.x = f2tf(v.x); lo.x = f2tf(v.x - hi.x);
            hi.y = f2tf(v.y); lo.y = f2tf(v.y - hi.y);
            hi.z = f2tf(v.z); lo.z = f2tf(v.z - hi.z);
            hi.w = f2tf(v.w); lo.w = f2tf(v.w - hi.w);
            *(float4*)&As[0][r][c4 * 4] = hi;
            *(float4*)&As[1][r][c4 * 4] = lo;
        }
#pragma unroll
        for (int ii = 0; ii < 2; ii++) {
            int i = tid + ii * 256;
            int r = i >> 5, c4 = i & 31;
            float4 v = *(const float4*)(W + (size_t)(kb * 16 + r) * 128 + c4 * 4);
            float4 hi, lo;
            hi.x = f2tf(v.x); lo.x = f2tf(v.x - hi.x);
            hi.y = f2tf(v.y); lo.y = f2tf(v.y - hi.y);
            hi.z = f2tf(v.z); lo.z = f2tf(v.z - hi.z);
            hi.w = f2tf(v.w); lo.w = f2tf(v.w - hi.w);
            *(float4*)&Bs[0][r][c4 * 4] = hi;
            *(float4*)&Bs[1][r][c4 * 4] = lo;
        }
        __syncthreads();

#pragma unroll
        for (int ks = 0; ks < 2; ks++) {
            int k0 = ks * 8;
            unsigned ah[2][4], al[2][4];
#pragma unroll
            for (int mt = 0; mt < 2; mt++) {
                int r = wm * 32 + mt * 16 + gid;
                int c = k0 + tig;
                ah[mt][0] = __float_as_uint(As[0][r][c]);
                ah[mt][1] = __float_as_uint(As[0][r + 8][c]);
                ah[mt][2] = __float_as_uint(As[0][r][c + 4]);
                ah[mt][3] = __float_as_uint(As[0][r + 8][c + 4]);
                al[mt][0] = __float_as_uint(As[1][r][c]);
                al[mt][1] = __float_as_uint(As[1][r + 8][c]);
                al[mt][2] = __float_as_uint(As[1][r][c + 4]);
                al[mt][3] = __float_as_uint(As[1][r + 8][c + 4]);
            }
#pragma unroll
            for (int nt = 0; nt < 8; nt++) {
                int kk = k0 + tig;
                int nn0 = wn * 64 + nt * 8 + gid;
                unsigned bh0 = __float_as_uint(Bs[0][kk][nn0]);
                unsigned bh1 = __float_as_uint(Bs[0][kk + 4][nn0]);
                unsigned bl0 = __float_as_uint(Bs[1][kk][nn0]);
                unsigned bl1 = __float_as_uint(Bs[1][kk + 4][nn0]);
#pragma unroll
                for (int mt = 0; mt < 2; mt++) {
                    mma_tf32(acc[mt][nt], ah[mt], bh0, bh1);
                    mma_tf32(acc[mt][nt], ah[mt], bl0, bl1);
                    mma_tf32(acc[mt][nt], al[mt], bh0, bh1);
                }
            }
        }
        __syncthreads();
    }

#pragma unroll
    for (int nt = 0; nt < 8; nt++) {
        int c = wn * 64 + nt * 8 + tig * 2;
        float b0 = __ldg(bias + c), b1 = __ldg(bias + c + 1);
#pragma unroll
        for (int mt = 0; mt < 2; mt++) {
            int r = row0 + wm * 32 + mt * 16 + gid;
            if (r < NN) {
                float2 o0 = make_float2(acc[mt][nt][0] + b0, acc[mt][nt][1] + b1);
                *(float2*)(out + (size_t)r * 128 + c) = o0;
            }
            if (r + 8 < NN) {
                float2 o1 = make_float2(acc[mt][nt][2] + b0, acc[mt][nt][3] + b1);
                *(float2*)(out + (size_t)(r + 8) * 128 + c) = o1;
            }
        }
    }
}

// ---- unrolled gather core: sum4 += coef[nbr[j]] * in[nbr[j], lane] over [s0,e0) ----
// also accumulates css += coef (scalar, for fused aggr). Unconditional loads, MLP=4.
__device__ __forceinline__ void gather4(const int* __restrict__ nbr,
                                        const float* __restrict__ coef,
                                        const float* __restrict__ in,
                                        int s0, int e0, int lane,
                                        float4& sum, float& css) {
    int j = s0;
    int e4 = s0 + ((e0 - s0) & ~3);
    for (; j < e4; j += 4) {
        int n0 = __ldg(nbr + j), n1 = __ldg(nbr + j + 1);
        int n2 = __ldg(nbr + j + 2), n3 = __ldg(nbr + j + 3);
        float c0 = __ldg(coef + n0), c1 = __ldg(coef + n1);
        float c2 = __ldg(coef + n2), c3 = __ldg(coef + n3);
        float4 v0 = *(const float4*)(in + (size_t)n0 * DD + lane * 4);
        float4 v1 = *(const float4*)(in + (size_t)n1 * DD + lane * 4);
        float4 v2 = *(const float4*)(in + (size_t)n2 * DD + lane * 4);
        float4 v3 = *(const float4*)(in + (size_t)n3 * DD + lane * 4);
        css += (c0 + c1) + (c2 + c3);
        sum.x = fmaf(c0, v0.x, sum.x); sum.y = fmaf(c0, v0.y, sum.y);
        sum.z = fmaf(c0, v0.z, sum.z); sum.w = fmaf(c0, v0.w, sum.w);
        sum.x = fmaf(c1, v1.x, sum.x); sum.y = fmaf(c1, v1.y, sum.y);
        sum.z = fmaf(c1, v1.z, sum.z); sum.w = fmaf(c1, v1.w, sum.w);
        sum.x = fmaf(c2, v2.x, sum.x); sum.y = fmaf(c2, v2.y, sum.y);
        sum.z = fmaf(c2, v2.z, sum.z); sum.w = fmaf(c2, v2.w, sum.w);
        sum.x = fmaf(c3, v3.x, sum.x); sum.y = fmaf(c3, v3.y, sum.y);
        sum.z = fmaf(c3, v3.z, sum.z); sum.w = fmaf(c3, v3.w, sum.w);
    }
    for (; j < e0; j++) {
        int n = __ldg(nbr + j);
        float c = __ldg(coef + n);
        float4 v = *(const float4*)(in + (size_t)n * DD + lane * 4);
        css += c;
        sum.x = fmaf(c, v.x, sum.x); sum.y = fmaf(c, v.y, sum.y);
        sum.z = fmaf(c, v.z, sum.z); sum.w = fmaf(c, v.w, sum.w);
    }
}

// ---------- GCN SpMM: out[w] = init[w] + dis[w] * sum_j dis[nbr]*in[nbr] ----------
__global__ void k_spmm_gcn(const int* __restrict__ ptr, const int* __restrict__ nbr,
                           const float* __restrict__ dis,
                           const float* __restrict__ in, const float* __restrict__ init,
                           float* __restrict__ out) {
    int w = (blockIdx.x * blockDim.x + threadIdx.x) >> 5;
    int lane = threadIdx.x & 31;
    if (w >= NN) return;
    float4 acc;
    if (init) acc = *(const float4*)(init + (size_t)w * DD + lane * 4);
    else      acc = make_float4(0.f, 0.f, 0.f, 0.f);
    float dw = dis[w];
    if (dw != 0.f) {
        float4 sum = make_float4(0.f, 0.f, 0.f, 0.f);
        float dummy = 0.f;
        gather4(nbr, dis, in, ptr[w], ptr[w + 1], lane, sum, dummy);
        acc.x = fmaf(dw, sum.x, acc.x);
        acc.y = fmaf(dw, sum.y, acc.y);
        acc.z = fmaf(dw, sum.z, acc.z);
        acc.w = fmaf(dw, sum.w, acc.w);
    }
    *(float4*)(out + (size_t)w * DD + lane * 4) = acc;
}

// ---------- down WEC fused single-pass: h2 + aggr + r + score/key (col-CSR) ----------
__global__ void k_wec_down(const float* __restrict__ s, const float* __restrict__ in,
                           const float* __restrict__ p,
                           float* __restrict__ out, float* __restrict__ r_out) {
    int w = (blockIdx.x * blockDim.x + threadIdx.x) >> 5;
    int lane = threadIdx.x & 31;
    if (w >= NN) return;
    float mw = g_maskf[w];
    float4 acc = make_float4(0.f, 0.f, 0.f, 0.f);
    if (mw > 0.f) {
        float4 sum = make_float4(0.f, 0.f, 0.f, 0.f);
        float ss = 0.f;
        gather4(g_erow_c, s, in, g_colptr[w], g_colptr[w + 1], lane, sum, ss);
        float aggr = ss + 1e-12f;
        float inv = 1.f / aggr;
        if (lane == 0) { g_aggr[w] = aggr; r_out[w] = inv; }
        acc.x = inv * sum.x; acc.y = inv * sum.y;
        acc.z = inv * sum.z; acc.w = inv * sum.w;
    } else if (lane == 0) {
        r_out[w] = 0.f;
    }
    *(float4*)(out + (size_t)w * DD + lane * 4) = acc;
    const float4 pv = *(const float4*)(p + lane * 4);
    float d = acc.x * pv.x + acc.y * pv.y + acc.z * pv.z + acc.w * pv.w;
    for (int o = 16; o; o >>= 1) d += __shfl_xor_sync(0xffffffffu, d, o);
    if (lane == 0) {
        float sc = d / g_pnorm;
        g_score[w] = sc;
        unsigned u = __float_as_uint(sc);
        unsigned key = (u & 0x80000000u) ? ~u : (u | 0x80000000u);
        g_key[w] = (mw > 0.f) ? key : 0u;
    }
}

// ---------- up WEC: out[w] = s[w] * sum_j r[nbr]*x[nbr]  (row-CSR) ----------
__global__ void k_wec_up(const float* __restrict__ s, const float* __restrict__ r,
                         const float* __restrict__ in, float* __restrict__ out) {
    int w = (blockIdx.x * blockDim.x + threadIdx.x) >> 5;
    int lane = threadIdx.x & 31;
    if (w >= NN) return;
    float sw = s[w];
    float4 acc = make_float4(0.f, 0.f, 0.f, 0.f);
    if (sw != 0.f) {
        float4 sum = make_float4(0.f, 0.f, 0.f, 0.f);
        float dummy = 0.f;
        gather4(g_ecol_r, r, in, g_rowptr[w], g_rowptr[w + 1], lane, sum, dummy);
        acc.x = sw * sum.x; acc.y = sw * sum.y;
        acc.z = sw * sum.z; acc.w = sw * sum.w;
    }
    *(float4*)(out + (size_t)w * DD + lane * 4) = acc;
}

// ---------------- top-k ----------------
__global__ void k_pnorm(const float* __restrict__ p) {
    __shared__ float sh[128];
    int t = threadIdx.x;
    float v = p[t];
    sh[t] = v * v;
    __syncthreads();
    for (int o = 64; o; o >>= 1) { if (t < o) sh[t] += sh[t + o]; __syncthreads(); }
    if (t == 0) g_pnorm = sqrtf(sh[0]);
}

__global__ void k_topk_init(unsigned k) {
    int t = threadIdx.x;
    if (t < 256) g_bins[t] = 0u;
    if (t == 0) { g_prefix = 0u; g_krem = k; }
}

__global__ void k_hist(int pass) {
    __shared__ unsigned hb[256];
    int t = threadIdx.x;
    if (t < 256) hb[t] = 0u;
    __syncthreads();
    unsigned pref = g_prefix;
    int shift = 24 - 8 * pass;
    for (int n = blockIdx.x * blockDim.x + t; n < NN; n += gridDim.x * blockDim.x) {
        unsigned key = g_key[n];
        bool ok = (pass == 0) || ((key >> (32 - 8 * pass)) == pref);
        if (ok) atomicAdd(&hb[(key >> shift) & 255u], 1u);
    }
    __syncthreads();
    if (t < 256 && hb[t]) atomicAdd(&g_bins[t], hb[t]);
}

__global__ void k_select() {
    __shared__ unsigned s[256];
    int t = threadIdx.x;
    unsigned v = g_bins[t];
    unsigned krem = g_krem;
    s[t] = v;
    __syncthreads();
    for (int off = 1; off < 256; off <<= 1) {
        unsigned add = (t + off < 256) ? s[t + off] : 0u;
        __syncthreads();
        s[t] += add;
        __syncthreads();
    }
    unsigned suf = s[t];
    unsigned sufN = (t < 255) ? s[t + 1] : 0u;
    if (suf >= krem && sufN < krem) {
        g_prefix = (g_prefix << 8) | (unsigned)t;
        g_krem = krem - sufN;
    }
    g_bins[t] = 0u;
}

__global__ void k_keptscale(const float* __restrict__ in, float* __restrict__ out) {
    int w = (blockIdx.x * blockDim.x + threadIdx.x) >> 5;
    int lane = threadIdx.x & 31;
    if (w >= NN) return;
    float scale = 0.f;
    if (lane == 0) {
        unsigned thr = g_prefix;
        float kept = (g_key[w] >= thr) ? 1.f : 0.f;
        g_maskf[w] = kept;
        g_weights[w] = g_aggr[w] * kept;
        scale = (kept != 0.f) ? tanhf(g_score[w]) : 0.f;
    }
    scale = __shfl_sync(0xffffffffu, scale, 0);
    float4 v = *(const float4*)(in + (size_t)w * DD + lane * 4);
    v.x *= scale; v.y *= scale; v.z *= scale; v.w *= scale;
    *(float4*)(out + (size_t)w * DD + lane * 4) = v;
}

// ---------------- host sequence ----------------
extern "C" void kernel_launch(void* const* d_in, const int* in_sizes, int n_in,
                              void* d_out, int out_size) {
    const float* x_in = (const float*)d_in[0];
    const int*   ei   = (const int*)d_in[1];
    const int*   row  = ei;
    const int*   col  = ei + EE;
    const float* Wd = (const float*)d_in[2];
    const float* bd = (const float*)d_in[3];
    const float* Wu = (const float*)d_in[4];
    const float* bu = (const float*)d_in[5];
    const float* Wb = (const float*)d_in[6];
    const float* bb = (const float*)d_in[7];
    const float* pv = (const float*)d_in[8];
    float* out = (float*)d_out;

    void *pt, *ph, *ph2, *px, *pd0, *pd1;
    void *pcolptr, *prowptr, *perowc, *pecolr;
    void *pdis0, *pdis1, *pdis2, *ps0, *ps1, *ps2, *pr0, *pr1;
    cudaGetSymbolAddress(&pt,  g_t);   cudaGetSymbolAddress(&ph,  g_h);
    cudaGetSymbolAddress(&ph2, g_h2);  cudaGetSymbolAddress(&px,  g_x);
    cudaGetSymbolAddress(&pd0, g_d0);  cudaGetSymbolAddress(&pd1, g_d1);
    cudaGetSymbolAddress(&pcolptr, g_colptr); cudaGetSymbolAddress(&prowptr, g_rowptr);
    cudaGetSymbolAddress(&perowc, g_erow_c);  cudaGetSymbolAddress(&pecolr, g_ecol_r);
    cudaGetSymbolAddress(&pdis0, g_dis0); cudaGetSymbolAddress(&pdis1, g_dis1);
    cudaGetSymbolAddress(&pdis2, g_dis2);
    cudaGetSymbolAddress(&ps0, g_s0); cudaGetSymbolAddress(&ps1, g_s1);
    cudaGetSymbolAddress(&ps2, g_s2);
    cudaGetSymbolAddress(&pr0, g_r0); cudaGetSymbolAddress(&pr1, g_r1);

    float *t = (float*)pt, *h = (float*)ph, *h2 = (float*)ph2, *x = (float*)px;
    float *d0 = (float*)pd0, *d1 = (float*)pd1;
    int *colptr = (int*)pcolptr, *rowptr = (int*)prowptr;
    int *erowc = (int*)perowc, *ecolr = (int*)pecolr;
    float *dis0 = (float*)pdis0, *dis1 = (float*)pdis1, *dis2 = (float*)pdis2;
    float *s0 = (float*)ps0, *s1 = (float*)ps1, *s2 = (float*)ps2;
    float *r0 = (float*)pr0, *r1 = (float*)pr1;

    const int GN = (NN + 255) / 256;       // 196
    const int GE = (EE + 255) / 256;       // 3125
    const int GW = (NN * 32 + 255) / 256;  // 6250 (warp per node)
    const int GG = (NN + 127) / 128;       // 391

    // ---- setup ----
    k_init<<<GN, 256>>>();
    k_edge_hist<<<GE, 256>>>(row, col);
    k_bsum<<<GN, 256>>>();
    k_bscan<<<1, 256>>>(GN);
    k_scan3<<<GN, 256>>>();
    k_fill<<<GE, 256>>>(row, col);

    auto GCN = [&](const float* in, const float* W, const float* b,
                   const float* dis, const float* init, float* o) {
        k_gemm_tc<<<GG, 256>>>(in, W, b, t);
        k_spmm_gcn<<<GW, 256>>>(colptr, erowc, dis, t, init, o);
    };
    auto TOPK = [&](unsigned k, const float* hin, float* xout) {
        k_topk_init<<<1, 256>>>(k);
        for (int pass = 0; pass < 4; pass++) {
            k_hist<<<GN, 256>>>(pass);
            k_select<<<1, 256>>>();
        }
        k_keptscale<<<GW, 256>>>(hin, xout);
    };

    // ---- down layer 0 ----
    k_degdis0<<<GN, 256>>>(dis0, s0);
    k_pnorm<<<1, 128>>>(pv);
    GCN(x_in, Wd + 0 * DD * DD, bd + 0 * DD, dis0, nullptr, h);
    GCN(h,    Wd + 1 * DD * DD, bd + 1 * DD, dis0, nullptr, d0);
    k_wec_down<<<GW, 256>>>(s0, d0, pv, h2, r0);
    TOPK(25000u, h2, x);

    // ---- down layer 1 ----
    k_degdis<<<GW, 256>>>(dis1, s1);
    k_pnorm<<<1, 128>>>(pv + DD);
    GCN(x, Wd + 2 * DD * DD, bd + 2 * DD, dis1, nullptr, h);
    GCN(h, Wd + 3 * DD * DD, bd + 3 * DD, dis1, nullptr, d1);
    k_wec_down<<<GW, 256>>>(s1, d1, pv + DD, h2, r1);
    TOPK(12500u, h2, x);

    // ---- bottom ----
    k_degdis<<<GW, 256>>>(dis2, s2);
    GCN(x, Wb + 0 * DD * DD, bb + 0 * DD, dis2, nullptr, h);
    GCN(h, Wb + 1 * DD * DD, bb + 1 * DD, dis2, nullptr, x);

    // ---- up layer 0 (level-1 masks; residual d1) ----
    k_wec_up<<<GW, 256>>>(s1, r1, x, h);
    GCN(h,  Wu + 0 * DD * DD, bu + 0 * DD, dis1, nullptr, h2);
    GCN(h2, Wu + 1 * DD * DD, bu + 1 * DD, dis1, d1, x);

    // ---- up layer 1 (level-0 masks; residual d0) -> output ----
    k_wec_up<<<GW, 256>>>(s0, r0, x, h);
    GCN(h,  Wu + 2 * DD * DD, bu + 2 * DD, dis0, nullptr, h2);
    GCN(h2, Wu + 3 * DD * DD, bu + 3 * DD, dis0, d0, out);
}

// round 6
// speedup vs baseline: 1.4521x; 1.0539x over previous
#include <cuda_runtime.h>
#include <math.h>

#define NN 50000
#define DD 128
#define EE 800000

// ---------------- device scratch ----------------
__device__ __align__(16) float g_t [NN*DD];
__device__ __align__(16) float g_h [NN*DD];
__device__ __align__(16) float g_h2[NN*DD];
__device__ __align__(16) float g_x [NN*DD];
__device__ __align__(16) float g_d0[NN*DD];
__device__ __align__(16) float g_d1[NN*DD];

__device__ int g_cntc[NN], g_cntr[NN];
__device__ int g_colptr[NN+1], g_rowptr[NN+1];
__device__ int g_nextc[NN], g_nextr[NN];
__device__ int g_erow_c[EE];   // col-CSR: neighbor = row endpoint
__device__ int g_ecol_r[EE];   // row-CSR: neighbor = col endpoint

__device__ int g_bsc[256], g_bsr[256], g_boc[256], g_bor[256];

__device__ float g_dis0[NN], g_dis1[NN], g_dis2[NN];
__device__ float g_s0[NN], g_s1[NN], g_s2[NN];
__device__ float g_r0[NN], g_r1[NN];
__device__ float g_maskf[NN], g_weights[NN], g_aggr[NN];
__device__ float g_score[NN];
__device__ unsigned g_key[NN];
__device__ unsigned g_bins[256];
__device__ unsigned g_prefix, g_krem;
__device__ float g_pnorm;
__device__ int g_list1[NN], g_list2[NN];
__device__ int g_nact;

// ---------------- setup ----------------
__global__ void k_init() {
    int i = blockIdx.x * blockDim.x + threadIdx.x;
    if (i < NN) { g_cntc[i] = 0; g_cntr[i] = 0; g_maskf[i] = 1.f; g_weights[i] = 1.f; }
}

__global__ void k_edge_hist(const int* __restrict__ row, const int* __restrict__ col) {
    int e = blockIdx.x * blockDim.x + threadIdx.x;
    if (e < EE) { atomicAdd(&g_cntc[col[e]], 1); atomicAdd(&g_cntr[row[e]], 1); }
}

__global__ void k_bsum() {
    __shared__ int sc[8], sr[8];
    int t = threadIdx.x;
    int i = blockIdx.x * 256 + t;
    int vc = (i < NN) ? g_cntc[i] : 0;
    int vr = (i < NN) ? g_cntr[i] : 0;
    for (int o = 16; o; o >>= 1) {
        vc += __shfl_xor_sync(0xffffffffu, vc, o);
        vr += __shfl_xor_sync(0xffffffffu, vr, o);
    }
    if ((t & 31) == 0) { sc[t >> 5] = vc; sr[t >> 5] = vr; }
    __syncthreads();
    if (t == 0) {
        int ac = 0, ar = 0;
        for (int w = 0; w < 8; w++) { ac += sc[w]; ar += sr[w]; }
        g_bsc[blockIdx.x] = ac; g_bsr[blockIdx.x] = ar;
    }
}

__global__ void k_bscan(int nblk) {
    __shared__ int s1[8], s2[8];
    int t = threadIdx.x, lane = t & 31, w = t >> 5;
    int vc = (t < nblk) ? g_bsc[t] : 0;
    int vr = (t < nblk) ? g_bsr[t] : 0;
    int ic = vc, ir = vr;
    for (int o = 1; o < 32; o <<= 1) {
        int nc = __shfl_up_sync(0xffffffffu, ic, o);
        int nr = __shfl_up_sync(0xffffffffu, ir, o);
        if (lane >= o) { ic += nc; ir += nr; }
    }
    if (lane == 31) { s1[w] = ic; s2[w] = ir; }
    __syncthreads();
    if (w == 0) {
        int a = (lane < 8) ? s1[lane] : 0;
        int b = (lane < 8) ? s2[lane] : 0;
        for (int o = 1; o < 8; o <<= 1) {
            int na = __shfl_up_sync(0xffffffffu, a, o);
            int nb = __shfl_up_sync(0xffffffffu, b, o);
            if (lane >= o) { a += na; b += nb; }
        }
        if (lane < 8) { s1[lane] = a; s2[lane] = b; }
    }
    __syncthreads();
    int offc = (w == 0) ? 0 : s1[w - 1];
    int offr = (w == 0) ? 0 : s2[w - 1];
    if (t < nblk) { g_boc[t] = offc + ic - vc; g_bor[t] = offr + ir - vr; }
}

__device__ __forceinline__ int blk_exscan(int v, int* ws) {
    __syncthreads();
    int lane = threadIdx.x & 31, w = threadIdx.x >> 5;
    int inc = v;
    for (int o = 1; o < 32; o <<= 1) {
        int n = __shfl_up_sync(0xffffffffu, inc, o);
        if (lane >= o) inc += n;
    }
    if (lane == 31) ws[w] = inc;
    __syncthreads();
    if (w == 0) {
        int s = (lane < 8) ? ws[lane] : 0;
        for (int o = 1; o < 8; o <<= 1) {
            int n = __shfl_up_sync(0xffffffffu, s, o);
            if (lane >= o) s += n;
        }
        if (lane < 8) ws[lane] = s;
    }
    __syncthreads();
    int woff = (w == 0) ? 0 : ws[w - 1];
    return woff + inc - v;
}

__global__ void k_scan3() {
    __shared__ int ws[8];
    int t = threadIdx.x;
    int i = blockIdx.x * 256 + t;
    int vc = (i < NN) ? g_cntc[i] : 0;
    int vr = (i < NN) ? g_cntr[i] : 0;
    int exc = blk_exscan(vc, ws);
    int exr = blk_exscan(vr, ws);
    if (i < NN) {
        int pc = g_boc[blockIdx.x] + exc; g_colptr[i] = pc; g_nextc[i] = pc;
        int pr = g_bor[blockIdx.x] + exr; g_rowptr[i] = pr; g_nextr[i] = pr;
    }
    if (i == 0) { g_colptr[NN] = EE; g_rowptr[NN] = EE; }
}

__global__ void k_fill(const int* __restrict__ row, const int* __restrict__ col) {
    int e = blockIdx.x * blockDim.x + threadIdx.x;
    if (e < EE) {
        int r = row[e], c = col[e];
        int p = atomicAdd(&g_nextc[c], 1); g_erow_c[p] = r;
        int q = atomicAdd(&g_nextr[r], 1); g_ecol_r[q] = c;
    }
}

// level-0 closed form: mask all ones -> deg = out-degree
__global__ void k_degdis0(float* __restrict__ dis_out, float* __restrict__ s_out) {
    int w = blockIdx.x * blockDim.x + threadIdx.x;
    if (w >= NN) return;
    float deg = (float)(g_rowptr[w + 1] - g_rowptr[w]);
    dis_out[w] = (deg > 0.f) ? rsqrtf(deg) : 0.f;
    s_out[w]   = (deg > 0.f) ? 1.f / deg : 0.f;
}

// general: deg over active out-edges (row-CSR)
__global__ void k_degdis(float* __restrict__ dis_out, float* __restrict__ s_out) {
    int w = (blockIdx.x * blockDim.x + threadIdx.x) >> 5;
    int lane = threadIdx.x & 31;
    if (w >= NN) return;
    float mw = g_maskf[w];
    if (mw == 0.f) {
        if (lane == 0) { dis_out[w] = 0.f; s_out[w] = 0.f; }
        return;
    }
    int s0 = g_rowptr[w], e0 = g_rowptr[w + 1];
    float sum = 0.f;
    for (int j = s0 + lane; j < e0; j += 32) sum += g_maskf[g_ecol_r[j]];
    for (int o = 16; o; o >>= 1) sum += __shfl_xor_sync(0xffffffffu, sum, o);
    if (lane == 0) {
        float deg = sum;
        dis_out[w] = (deg > 0.f) ? rsqrtf(deg) : 0.f;
        s_out[w]   = (deg > 0.f) ? g_weights[w] / deg : 0.f;
    }
}

// ---------------- tensor-core GEMM (3xTF32), optional compacted row list ----------------
__device__ __forceinline__ float f2tf(float a) {
    unsigned u;
    asm("cvt.rna.tf32.f32 %0, %1;" : "=r"(u) : "f"(a));
    return __uint_as_float(u);
}

__device__ __forceinline__ void mma_tf32(float* d, const unsigned* a, unsigned b0, unsigned b1) {
    asm volatile(
        "mma.sync.aligned.m16n8k8.row.col.f32.tf32.tf32.f32 "
        "{%0,%1,%2,%3}, {%4,%5,%6,%7}, {%8,%9}, {%0,%1,%2,%3};"
        : "+f"(d[0]), "+f"(d[1]), "+f"(d[2]), "+f"(d[3])
        : "r"(a[0]), "r"(a[1]), "r"(a[2]), "r"(a[3]), "r"(b0), "r"(b1));
}

__global__ void __launch_bounds__(256, 1)
k_gemm_tc(const float* __restrict__ X, const float* __restrict__ W,
          const float* __restrict__ bias, float* __restrict__ out,
          const int* __restrict__ rowlist, int nrows) {
    __shared__ __align__(16) float As[2][128][20];
    __shared__ __align__(16) float Bs[2][16][132];
    __shared__ int rmap[128];
    int tid  = threadIdx.x;
    int lane = tid & 31;
    int warp = tid >> 5;
    int wm = warp & 3;
    int wn = warp >> 2;
    int gid = lane >> 2;
    int tig = lane & 3;
    int row0 = blockIdx.x * 128;

    // resolve row mapping once
    if (tid < 128) {
        int ridx = row0 + tid;
        int gr = -1;
        if (ridx < nrows) gr = rowlist ? rowlist[ridx] : ridx;
        rmap[tid] = gr;
    }
    __syncthreads();

    float acc[2][8][4];
#pragma unroll
    for (int mt = 0; mt < 2; mt++)
#pragma unroll
        for (int nt = 0; nt < 8; nt++)
#pragma unroll
            for (int q = 0; q < 4; q++) acc[mt][nt][q] = 0.f;

    for (int kb = 0; kb < 8; kb++) {
#pragma unroll
        for (int ii = 0; ii < 2; ii++) {
            int i = tid + ii * 256;
            int r = i >> 2, c4 = i & 3;
            int gr = rmap[r];
            float4 v = make_float4(0.f, 0.f, 0.f, 0.f);
            if (gr >= 0) v = *(const float4*)(X + (size_t)gr * 128 + kb * 16 + c4 * 4);
            float4 hi, lo;
            hi.x = f2tf(v.x); lo.x = f2tf(v.x - hi.x);
            hi.y = f2tf(v.y); lo.y = f2tf(v.y - hi.y);
            hi.z = f2tf(v.z); lo.z = f2tf(v.z - hi.z);
            hi.w = f2tf(v.w); lo.w = f2tf(v.w - hi.w);
            *(float4*)&As[0][r][c4 * 4] = hi;
            *(float4*)&As[1][r][c4 * 4] = lo;
        }
#pragma unroll
        for (int ii = 0; ii < 2; ii++) {
            int i = tid + ii * 256;
            int r = i >> 5, c4 = i & 31;
            float4 v = *(const float4*)(W + (size_t)(kb * 16 + r) * 128 + c4 * 4);
            float4 hi, lo;
            hi.x = f2tf(v.x); lo.x = f2tf(v.x - hi.x);
            hi.y = f2tf(v.y); lo.y = f2tf(v.y - hi.y);
            hi.z = f2tf(v.z); lo.z = f2tf(v.z - hi.z);
            hi.w = f2tf(v.w); lo.w = f2tf(v.w - hi.w);
            *(float4*)&Bs[0][r][c4 * 4] = hi;
            *(float4*)&Bs[1][r][c4 * 4] = lo;
        }
        __syncthreads();

#pragma unroll
        for (int ks = 0; ks < 2; ks++) {
            int k0 = ks * 8;
            unsigned ah[2][4], al[2][4];
#pragma unroll
            for (int mt = 0; mt < 2; mt++) {
                int r = wm * 32 + mt * 16 + gid;
                int c = k0 + tig;
                ah[mt][0] = __float_as_uint(As[0][r][c]);
                ah[mt][1] = __float_as_uint(As[0][r + 8][c]);
                ah[mt][2] = __float_as_uint(As[0][r][c + 4]);
                ah[mt][3] = __float_as_uint(As[0][r + 8][c + 4]);
                al[mt][0] = __float_as_uint(As[1][r][c]);
                al[mt][1] = __float_as_uint(As[1][r + 8][c]);
                al[mt][2] = __float_as_uint(As[1][r][c + 4]);
                al[mt][3] = __float_as_uint(As[1][r + 8][c + 4]);
            }
#pragma unroll
            for (int nt = 0; nt < 8; nt++) {
                int kk = k0 + tig;
                int nn0 = wn * 64 + nt * 8 + gid;
                unsigned bh0 = __float_as_uint(Bs[0][kk][nn0]);
                unsigned bh1 = __float_as_uint(Bs[0][kk + 4][nn0]);
                unsigned bl0 = __float_as_uint(Bs[1][kk][nn0]);
                unsigned bl1 = __float_as_uint(Bs[1][kk + 4][nn0]);
#pragma unroll
                for (int mt = 0; mt < 2; mt++) {
                    mma_tf32(acc[mt][nt], ah[mt], bh0, bh1);
                    mma_tf32(acc[mt][nt], ah[mt], bl0, bl1);
                    mma_tf32(acc[mt][nt], al[mt], bh0, bh1);
                }
            }
        }
        __syncthreads();
    }

#pragma unroll
    for (int nt = 0; nt < 8; nt++) {
        int c = wn * 64 + nt * 8 + tig * 2;
        float b0 = __ldg(bias + c), b1 = __ldg(bias + c + 1);
#pragma unroll
        for (int mt = 0; mt < 2; mt++) {
            int r = wm * 32 + mt * 16 + gid;
            int gr0 = rmap[r], gr1 = rmap[r + 8];
            if (gr0 >= 0) {
                float2 o0 = make_float2(acc[mt][nt][0] + b0, acc[mt][nt][1] + b1);
                *(float2*)(out + (size_t)gr0 * 128 + c) = o0;
            }
            if (gr1 >= 0) {
                float2 o1 = make_float2(acc[mt][nt][2] + b0, acc[mt][nt][3] + b1);
                *(float2*)(out + (size_t)gr1 * 128 + c) = o1;
            }
        }
    }
}

// ---- unrolled gather: MLP=4 on idx/coef chain, PREDICATED float4 row loads ----
__device__ __forceinline__ void gather4(const int* __restrict__ nbr,
                                        const float* __restrict__ coef,
                                        const float* __restrict__ in,
                                        int s0, int e0, int lane,
                                        float4& sum, float& css) {
    int j = s0;
    int e4 = s0 + ((e0 - s0) & ~3);
    for (; j < e4; j += 4) {
        int n0 = __ldg(nbr + j), n1 = __ldg(nbr + j + 1);
        int n2 = __ldg(nbr + j + 2), n3 = __ldg(nbr + j + 3);
        float c0 = __ldg(coef + n0), c1 = __ldg(coef + n1);
        float c2 = __ldg(coef + n2), c3 = __ldg(coef + n3);
        css += (c0 + c1) + (c2 + c3);
        if (c0 != 0.f) {
            float4 v = *(const float4*)(in + (size_t)n0 * DD + lane * 4);
            sum.x = fmaf(c0, v.x, sum.x); sum.y = fmaf(c0, v.y, sum.y);
            sum.z = fmaf(c0, v.z, sum.z); sum.w = fmaf(c0, v.w, sum.w);
        }
        if (c1 != 0.f) {
            float4 v = *(const float4*)(in + (size_t)n1 * DD + lane * 4);
            sum.x = fmaf(c1, v.x, sum.x); sum.y = fmaf(c1, v.y, sum.y);
            sum.z = fmaf(c1, v.z, sum.z); sum.w = fmaf(c1, v.w, sum.w);
        }
        if (c2 != 0.f) {
            float4 v = *(const float4*)(in + (size_t)n2 * DD + lane * 4);
            sum.x = fmaf(c2, v.x, sum.x); sum.y = fmaf(c2, v.y, sum.y);
            sum.z = fmaf(c2, v.z, sum.z); sum.w = fmaf(c2, v.w, sum.w);
        }
        if (c3 != 0.f) {
            float4 v = *(const float4*)(in + (size_t)n3 * DD + lane * 4);
            sum.x = fmaf(c3, v.x, sum.x); sum.y = fmaf(c3, v.y, sum.y);
            sum.z = fmaf(c3, v.z, sum.z); sum.w = fmaf(c3, v.w, sum.w);
        }
    }
    for (; j < e0; j++) {
        int n = __ldg(nbr + j);
        float c = __ldg(coef + n);
        css += c;
        if (c != 0.f) {
            float4 v = *(const float4*)(in + (size_t)n * DD + lane * 4);
            sum.x = fmaf(c, v.x, sum.x); sum.y = fmaf(c, v.y, sum.y);
            sum.z = fmaf(c, v.z, sum.z); sum.w = fmaf(c, v.w, sum.w);
        }
    }
}

// ---------- GCN SpMM: out[w] = init[w] + dis[w] * sum_j dis[nbr]*in[nbr] ----------
__global__ void k_spmm_gcn(const int* __restrict__ ptr, const int* __restrict__ nbr,
                           const float* __restrict__ dis,
                           const float* __restrict__ in, const float* __restrict__ init,
                           float* __restrict__ out) {
    int w = (blockIdx.x * blockDim.x + threadIdx.x) >> 5;
    int lane = threadIdx.x & 31;
    if (w >= NN) return;
    float4 acc;
    if (init) acc = *(const float4*)(init + (size_t)w * DD + lane * 4);
    else      acc = make_float4(0.f, 0.f, 0.f, 0.f);
    float dw = dis[w];
    if (dw != 0.f) {
        float4 sum = make_float4(0.f, 0.f, 0.f, 0.f);
        float dummy = 0.f;
        gather4(nbr, dis, in, ptr[w], ptr[w + 1], lane, sum, dummy);
        acc.x = fmaf(dw, sum.x, acc.x);
        acc.y = fmaf(dw, sum.y, acc.y);
        acc.z = fmaf(dw, sum.z, acc.z);
        acc.w = fmaf(dw, sum.w, acc.w);
    }
    *(float4*)(out + (size_t)w * DD + lane * 4) = acc;
}

// ---------- down WEC fused single-pass: h2 + aggr + r + score/key (col-CSR) ----------
__global__ void k_wec_down(const float* __restrict__ s, const float* __restrict__ in,
                           const float* __restrict__ p,
                           float* __restrict__ out, float* __restrict__ r_out) {
    int w = (blockIdx.x * blockDim.x + threadIdx.x) >> 5;
    int lane = threadIdx.x & 31;
    if (w >= NN) return;
    float mw = g_maskf[w];
    float4 acc = make_float4(0.f, 0.f, 0.f, 0.f);
    if (mw > 0.f) {
        float4 sum = make_float4(0.f, 0.f, 0.f, 0.f);
        float ss = 0.f;
        gather4(g_erow_c, s, in, g_colptr[w], g_colptr[w + 1], lane, sum, ss);
        float aggr = ss + 1e-12f;
        float inv = 1.f / aggr;
        if (lane == 0) { g_aggr[w] = aggr; r_out[w] = inv; }
        acc.x = inv * sum.x; acc.y = inv * sum.y;
        acc.z = inv * sum.z; acc.w = inv * sum.w;
    } else if (lane == 0) {
        r_out[w] = 0.f;
    }
    *(float4*)(out + (size_t)w * DD + lane * 4) = acc;
    const float4 pv = *(const float4*)(p + lane * 4);
    float d = acc.x * pv.x + acc.y * pv.y + acc.z * pv.z + acc.w * pv.w;
    for (int o = 16; o; o >>= 1) d += __shfl_xor_sync(0xffffffffu, d, o);
    if (lane == 0) {
        float sc = d / g_pnorm;
        g_score[w] = sc;
        unsigned u = __float_as_uint(sc);
        unsigned key = (u & 0x80000000u) ? ~u : (u | 0x80000000u);
        g_key[w] = (mw > 0.f) ? key : 0u;
    }
}

// ---------- up WEC: out[w] = s[w] * sum_j r[nbr]*x[nbr]  (row-CSR) ----------
__global__ void k_wec_up(const float* __restrict__ s, const float* __restrict__ r,
                         const float* __restrict__ in, float* __restrict__ out) {
    int w = (blockIdx.x * blockDim.x + threadIdx.x) >> 5;
    int lane = threadIdx.x & 31;
    if (w >= NN) return;
    float sw = s[w];
    float4 acc = make_float4(0.f, 0.f, 0.f, 0.f);
    if (sw != 0.f) {
        float4 sum = make_float4(0.f, 0.f, 0.f, 0.f);
        float dummy = 0.f;
        gather4(g_ecol_r, r, in, g_rowptr[w], g_rowptr[w + 1], lane, sum, dummy);
        acc.x = sw * sum.x; acc.y = sw * sum.y;
        acc.z = sw * sum.z; acc.w = sw * sum.w;
    }
    *(float4*)(out + (size_t)w * DD + lane * 4) = acc;
}

// ---------------- top-k ----------------
__global__ void k_pnorm(const float* __restrict__ p) {
    __shared__ float sh[128];
    int t = threadIdx.x;
    float v = p[t];
    sh[t] = v * v;
    __syncthreads();
    for (int o = 64; o; o >>= 1) { if (t < o) sh[t] += sh[t + o]; __syncthreads(); }
    if (t == 0) g_pnorm = sqrtf(sh[0]);
}

__global__ void k_topk_init(unsigned k) {
    int t = threadIdx.x;
    if (t < 256) g_bins[t] = 0u;
    if (t == 0) { g_prefix = 0u; g_krem = k; g_nact = 0; }
}

__global__ void k_hist(int pass) {
    __shared__ unsigned hb[256];
    int t = threadIdx.x;
    if (t < 256) hb[t] = 0u;
    __syncthreads();
    unsigned pref = g_prefix;
    int shift = 24 - 8 * pass;
    for (int n = blockIdx.x * blockDim.x + t; n < NN; n += gridDim.x * blockDim.x) {
        unsigned key = g_key[n];
        bool ok = (pass == 0) || ((key >> (32 - 8 * pass)) == pref);
        if (ok) atomicAdd(&hb[(key >> shift) & 255u], 1u);
    }
    __syncthreads();
    if (t < 256 && hb[t]) atomicAdd(&g_bins[t], hb[t]);
}

__global__ void k_select() {
    __shared__ unsigned s[256];
    int t = threadIdx.x;
    unsigned v = g_bins[t];
    unsigned krem = g_krem;
    s[t] = v;
    __syncthreads();
    for (int off = 1; off < 256; off <<= 1) {
        unsigned add = (t + off < 256) ? s[t + off] : 0u;
        __syncthreads();
        s[t] += add;
        __syncthreads();
    }
    unsigned suf = s[t];
    unsigned sufN = (t < 255) ? s[t + 1] : 0u;
    if (suf >= krem && sufN < krem) {
        g_prefix = (g_prefix << 8) | (unsigned)t;
        g_krem = krem - sufN;
    }
    g_bins[t] = 0u;
}

// fused kept + weights + mask + scale-x + active-list compaction (warp per node)
__global__ void k_keptscale(const float* __restrict__ in, float* __restrict__ out,
                            int* __restrict__ list) {
    int w = (blockIdx.x * blockDim.x + threadIdx.x) >> 5;
    int lane = threadIdx.x & 31;
    if (w >= NN) return;
    float scale = 0.f;
    if (lane == 0) {
        unsigned thr = g_prefix;
        float kept = (g_key[w] >= thr) ? 1.f : 0.f;
        g_maskf[w] = kept;
        g_weights[w] = g_aggr[w] * kept;
        if (kept != 0.f) {
            scale = tanhf(g_score[w]);
            int pos = atomicAdd(&g_nact, 1);
            list[pos] = w;
        }
    }
    scale = __shfl_sync(0xffffffffu, scale, 0);
    float4 v = *(const float4*)(in + (size_t)w * DD + lane * 4);
    v.x *= scale; v.y *= scale; v.z *= scale; v.w *= scale;
    *(float4*)(out + (size_t)w * DD + lane * 4) = v;
}

// ---------------- host sequence ----------------
extern "C" void kernel_launch(void* const* d_in, const int* in_sizes, int n_in,
                              void* d_out, int out_size) {
    const float* x_in = (const float*)d_in[0];
    const int*   ei   = (const int*)d_in[1];
    const int*   row  = ei;
    const int*   col  = ei + EE;
    const float* Wd = (const float*)d_in[2];
    const float* bd = (const float*)d_in[3];
    const float* Wu = (const float*)d_in[4];
    const float* bu = (const float*)d_in[5];
    const float* Wb = (const float*)d_in[6];
    const float* bb = (const float*)d_in[7];
    const float* pv = (const float*)d_in[8];
    float* out = (float*)d_out;

    void *pt, *ph, *ph2, *px, *pd0, *pd1;
    void *pcolptr, *prowptr, *perowc, *pecolr;
    void *pdis0, *pdis1, *pdis2, *ps0, *ps1, *ps2, *pr0, *pr1, *pl1, *pl2;
    cudaGetSymbolAddress(&pt,  g_t);   cudaGetSymbolAddress(&ph,  g_h);
    cudaGetSymbolAddress(&ph2, g_h2);  cudaGetSymbolAddress(&px,  g_x);
    cudaGetSymbolAddress(&pd0, g_d0);  cudaGetSymbolAddress(&pd1, g_d1);
    cudaGetSymbolAddress(&pcolptr, g_colptr); cudaGetSymbolAddress(&prowptr, g_rowptr);
    cudaGetSymbolAddress(&perowc, g_erow_c);  cudaGetSymbolAddress(&pecolr, g_ecol_r);
    cudaGetSymbolAddress(&pdis0, g_dis0); cudaGetSymbolAddress(&pdis1, g_dis1);
    cudaGetSymbolAddress(&pdis2, g_dis2);
    cudaGetSymbolAddress(&ps0, g_s0); cudaGetSymbolAddress(&ps1, g_s1);
    cudaGetSymbolAddress(&ps2, g_s2);
    cudaGetSymbolAddress(&pr0, g_r0); cudaGetSymbolAddress(&pr1, g_r1);
    cudaGetSymbolAddress(&pl1, g_list1); cudaGetSymbolAddress(&pl2, g_list2);

    float *t = (float*)pt, *h = (float*)ph, *h2 = (float*)ph2, *x = (float*)px;
    float *d0 = (float*)pd0, *d1 = (float*)pd1;
    int *colptr = (int*)pcolptr, *rowptr = (int*)prowptr;
    int *erowc = (int*)perowc, *ecolr = (int*)pecolr;
    float *dis0 = (float*)pdis0, *dis1 = (float*)pdis1, *dis2 = (float*)pdis2;
    float *s0 = (float*)ps0, *s1 = (float*)ps1, *s2 = (float*)ps2;
    float *r0 = (float*)pr0, *r1 = (float*)pr1;
    int *list1 = (int*)pl1, *list2 = (int*)pl2;

    const int GN = (NN + 255) / 256;       // 196
    const int GE = (EE + 255) / 256;       // 3125
    const int GW = (NN * 32 + 255) / 256;  // 6250 (warp per node)
    const int GG  = (NN + 127) / 128;      // 391 (full)
    const int GG1 = (25000 + 127) / 128;   // 196 (level-1 active)
    const int GG2 = (12500 + 127) / 128;   // 98  (level-2 active)

    // ---- setup ----
    k_init<<<GN, 256>>>();
    k_edge_hist<<<GE, 256>>>(row, col);
    k_bsum<<<GN, 256>>>();
    k_bscan<<<1, 256>>>(GN);
    k_scan3<<<GN, 256>>>();
    k_fill<<<GE, 256>>>(row, col);

    auto GCN = [&](const float* in, const float* W, const float* b,
                   const float* dis, const float* init, float* o,
                   const int* rl, int nr, int grid) {
        k_gemm_tc<<<grid, 256>>>(in, W, b, t, rl, nr);
        k_spmm_gcn<<<GW, 256>>>(colptr, erowc, dis, t, init, o);
    };
    auto TOPK = [&](unsigned k, const float* hin, float* xout, int* list) {
        k_topk_init<<<1, 256>>>(k);
        for (int pass = 0; pass < 4; pass++) {
            k_hist<<<GN, 256>>>(pass);
            k_select<<<1, 256>>>();
        }
        k_keptscale<<<GW, 256>>>(hin, xout, list);
    };

    // ---- down layer 0 (full density) ----
    k_degdis0<<<GN, 256>>>(dis0, s0);
    k_pnorm<<<1, 128>>>(pv);
    GCN(x_in, Wd + 0 * DD * DD, bd + 0 * DD, dis0, nullptr, h, nullptr, NN, GG);
    GCN(h,    Wd + 1 * DD * DD, bd + 1 * DD, dis0, nullptr, d0, nullptr, NN, GG);
    k_wec_down<<<GW, 256>>>(s0, d0, pv, h2, r0);
    TOPK(25000u, h2, x, list1);

    // ---- down layer 1 (25000 active) ----
    k_degdis<<<GW, 256>>>(dis1, s1);
    k_pnorm<<<1, 128>>>(pv + DD);
    GCN(x, Wd + 2 * DD * DD, bd + 2 * DD, dis1, nullptr, h, list1, 25000, GG1);
    GCN(h, Wd + 3 * DD * DD, bd + 3 * DD, dis1, nullptr, d1, list1, 25000, GG1);
    k_wec_down<<<GW, 256>>>(s1, d1, pv + DD, h2, r1);
    TOPK(12500u, h2, x, list2);

    // ---- bottom (12500 active) ----
    k_degdis<<<GW, 256>>>(dis2, s2);
    GCN(x, Wb + 0 * DD * DD, bb + 0 * DD, dis2, nullptr, h, list2, 12500, GG2);
    GCN(h, Wb + 1 * DD * DD, bb + 1 * DD, dis2, nullptr, x, list2, 12500, GG2);

    // ---- up layer 0 (level-1 masks, 25000 active; residual d1) ----
    k_wec_up<<<GW, 256>>>(s1, r1, x, h);
    GCN(h,  Wu + 0 * DD * DD, bu + 0 * DD, dis1, nullptr, h2, list1, 25000, GG1);
    GCN(h2, Wu + 1 * DD * DD, bu + 1 * DD, dis1, d1, x, list1, 25000, GG1);

    // ---- up layer 1 (level-0 masks, full; residual d0) -> output ----
    k_wec_up<<<GW, 256>>>(s0, r0, x, h);
    GCN(h,  Wu + 2 * DD * DD, bu + 2 * DD, dis0, nullptr, h2, nullptr, NN, GG);
    GCN(h2, Wu + 3 * DD * DD, bu + 3 * DD, dis0, d0, out, nullptr, NN, GG);
}